// round 11
// baseline (speedup 1.0000x reference)
#include <cuda_runtime.h>
#include <cuda_bf16.h>
#include <math.h>
#include <stdint.h>

#define NN 10000
#define EE 50000
#define EA 60000      // E + N self loops
#define ED 16
#define KBI 272
#define CBI 4352      // 272*16
#define CB2 8704      // 2*CBI
#define HMAX 512
#define KP 288        // KBI padded (bias row at 272), %32 == 0
#define NP 384        // KBI padded to N%128

// ---------------- scratch (static device globals; no runtime alloc) ----------------
__device__ __nv_bfloat16 g_xb[NN * 32];             // x converted to bf16
__device__ __nv_bfloat16 g_h1[NN * HMAX];
__device__ __nv_bfloat16 g_h2[NN * HMAX];
__device__ float g_xlr[NN * 1024];                  // [node][xl(dout) | xr(dout)]
__device__ float g_cnt[NN];
__device__ float g_msum[NN * ED];
__device__ float g_mean[NN * ED];
__device__ int   g_deg[NN];
__device__ int   g_off[NN + 1];
__device__ int   g_pos[NN];
__device__ int   g_eid[EA];
__device__ __nv_bfloat16 g_Wlr[HMAX * 1024];        // packed [K][Wl | Wr] bf16
__device__ __nv_bfloat16 g_UV[HMAX * CB2];          // packed [i][U | V] bf16
__device__ __nv_bfloat16 g_ABb[(size_t)NN * CB2];   // per-node factors, bf16
__device__ __nv_bfloat16 g_bib[(size_t)EE * KP];    // bilinear output + bias col, bf16
__device__ float g_m1[(size_t)EE * NP];             // relu(bi@Wm1+bm1)
__device__ __nv_bfloat16 g_Wm1p[KP * NP];           // padded Wm1 with bias row, bf16

// ---------------- helpers ----------------
__device__ __forceinline__ uint32_t bfpair(float lo, float hi) {
    __nv_bfloat162 h2 = __floats2bfloat162_rn(lo, hi);
    return *reinterpret_cast<uint32_t*>(&h2);
}
__device__ __forceinline__ void ldsm_x4(uint32_t& r0, uint32_t& r1, uint32_t& r2,
                                        uint32_t& r3, uint32_t addr) {
    asm volatile("ldmatrix.sync.aligned.m8n8.x4.shared.b16 {%0,%1,%2,%3}, [%4];"
                 : "=r"(r0), "=r"(r1), "=r"(r2), "=r"(r3) : "r"(addr));
}

// ---------------- edge_attr mean per dst (self-loop fill 'mean') ----------------
__global__ void k_count(const int* __restrict__ dst, const float* __restrict__ ea) {
    int idx = blockIdx.x * blockDim.x + threadIdx.x;
    if (idx >= EE * ED) return;
    int e = idx >> 4, j = idx & 15;
    int d = dst[e];
    atomicAdd(&g_msum[d * ED + j], ea[idx]);
    if (j == 0) atomicAdd(&g_cnt[d], 1.0f);
}
__global__ void k_mean() {
    int idx = blockIdx.x * blockDim.x + threadIdx.x;
    if (idx >= NN * ED) return;
    g_mean[idx] = g_msum[idx] / fmaxf(g_cnt[idx >> 4], 1.0f);
}

// ---------------- CSR build over augmented edges (dst = sort key) ----------------
__global__ void k_deg(const int* __restrict__ dst) {
    int e = blockIdx.x * blockDim.x + threadIdx.x;
    if (e >= EA) return;
    int d = (e < EE) ? dst[e] : (e - EE);
    atomicAdd(&g_deg[d], 1);
}
__global__ void k_scan() {   // single block, 1024 threads, warp-shuffle scan
    __shared__ int wsum[32];
    int tid = threadIdx.x, lane = tid & 31, w = tid >> 5;
    int base = 0;
    for (int start = 0; start < NN; start += 1024) {
        int i = start + tid;
        int x = (i < NN) ? g_deg[i] : 0;
#pragma unroll
        for (int o = 1; o < 32; o <<= 1) {
            int t = __shfl_up_sync(0xffffffffu, x, o);
            if (lane >= o) x += t;
        }
        if (lane == 31) wsum[w] = x;
        __syncthreads();
        if (w == 0) {
            int s = wsum[lane];
#pragma unroll
            for (int o = 1; o < 32; o <<= 1) {
                int t = __shfl_up_sync(0xffffffffu, s, o);
                if (lane >= o) s += t;
            }
            wsum[lane] = s;
        }
        __syncthreads();
        int off = (w > 0) ? wsum[w - 1] : 0;
        if (i < NN) g_off[i + 1] = base + off + x;
        base += wsum[31];
        __syncthreads();
    }
    if (tid == 0) g_off[0] = 0;
}
__global__ void k_fill(const int* __restrict__ dst) {
    int e = blockIdx.x * blockDim.x + threadIdx.x;
    if (e >= EA) return;
    int d = (e < EE) ? dst[e] : (e - EE);
    int p = atomicAdd(&g_pos[d], 1);
    g_eid[g_off[d] + p] = e;
}

// ---------------- x -> bf16 ----------------
__global__ void k_cvtx(const float* __restrict__ x) {
    int idx = blockIdx.x * blockDim.x + threadIdx.x;
    if (idx >= NN * 32 / 2) return;
    float2 v = *(const float2*)(x + idx * 2);
    *(uint32_t*)(g_xb + idx * 2) = bfpair(v.x, v.y);
}

// ------- BF16 tensor-core GEMM, bf16 operands in memory: C[M,N]=A[M,K]*B[K,N] ------------
// BM=BN=128, BK=32, 256 threads = 8 warps (4 in M x 2 in N), warp tile 32x64.
// ldmatrix fragment loads; double-buffered smem; raw-copy A staging, PRMT-interleave B.
// Requires: N % 128 == 0, K % 32 == 0. M arbitrary (guarded).
#define SROW 20
template <typename OutT, bool RELU>
__global__ __launch_bounds__(256) void bf16gemm(
        const __nv_bfloat16* __restrict__ A, const __nv_bfloat16* __restrict__ Bm,
        OutT* __restrict__ C, int M, int N, int K) {
    __shared__ uint32_t As[2][128 * SROW];
    __shared__ uint32_t Bs[2][128 * SROW];

    int tid = threadIdx.x;
    int lane = tid & 31, wid = tid >> 5;
    int g = lane >> 2, t = lane & 3;
    int wm = (wid & 3) * 32;
    int wn = (wid >> 2) * 64;
    int brow = blockIdx.y * 128;
    int bcol = blockIdx.x * 128;

    uint32_t smA = (uint32_t)__cvta_generic_to_shared(&As[0][0]);
    uint32_t smB = (uint32_t)__cvta_generic_to_shared(&Bs[0][0]);
    const uint32_t BUFB = 128 * SROW * 4;

    float c[2][8][4];
#pragma unroll
    for (int mi = 0; mi < 2; mi++)
#pragma unroll
        for (int nf = 0; nf < 8; nf++)
#pragma unroll
            for (int q = 0; q < 4; q++) c[mi][nf][q] = 0.0f;

    // A staging: thread covers row tid>>1, 16 bf16 at kpair offset (tid&1)*8
    int arow = tid >> 1;
    int ahalf = tid & 1;
    bool a_ok = (brow + arow) < M;
    const __nv_bfloat16* Aip = A + (size_t)(brow + arow) * K + ahalf * 16;
    uint4 a4[2];
    uint2 b2[2][2];

    auto load_regs = [&](int k0) {
        if (a_ok) {
            a4[0] = *(const uint4*)(Aip + k0);
            a4[1] = *(const uint4*)(Aip + k0 + 8);
        } else {
            a4[0] = make_uint4(0, 0, 0, 0);
            a4[1] = make_uint4(0, 0, 0, 0);
        }
#pragma unroll
        for (int s = 0; s < 2; s++) {
            int task = tid + s * 256;
            int kp = task >> 5, cg = task & 31;
            const __nv_bfloat16* bp = Bm + (size_t)(k0 + 2 * kp) * N + bcol + cg * 4;
            b2[s][0] = *(const uint2*)(bp);
            b2[s][1] = *(const uint2*)(bp + N);
        }
    };
    auto store_smem = [&](int buf) {
        {
            uint32_t* dst0 = &As[buf][arow * SROW + ahalf * 8];
            *(uint4*)dst0 = a4[0];
            *(uint4*)(dst0 + 4) = a4[1];
        }
#pragma unroll
        for (int s = 0; s < 2; s++) {
            int task = tid + s * 256;
            int kp = task >> 5, cg = task & 31;
            int seg = kp >> 2, kin = kp & 3;
            const uint32_t* w0 = (const uint32_t*)&b2[s][0];
            const uint32_t* w1 = (const uint32_t*)&b2[s][1];
#pragma unroll
            for (int j2 = 0; j2 < 2; j2++) {
                int col0 = cg * 4 + j2 * 2;
                int ps = seg ^ ((col0 >> 3) & 3);
                uint32_t p0 = __byte_perm(w0[j2], w1[j2], 0x5410);
                uint32_t p1 = __byte_perm(w0[j2], w1[j2], 0x7632);
                Bs[buf][col0 * SROW + ps * 4 + kin] = p0;
                Bs[buf][(col0 + 1) * SROW + ps * 4 + kin] = p1;
            }
        }
    };

    load_regs(0);
    store_smem(0);
    __syncthreads();

    int buf = 0;
    for (int k0 = 0; k0 < K; k0 += 32) {
        bool nxt = (k0 + 32) < K;
        if (nxt) load_regs(k0 + 32);
        uint32_t baseA = smA + buf * BUFB;
        uint32_t baseB = smB + buf * BUFB;
#pragma unroll
        for (int ks = 0; ks < 2; ks++) {
            uint32_t a[2][4], b[8][2];
#pragma unroll
            for (int mi = 0; mi < 2; mi++) {
                int row = wm + mi * 16 + (lane & 7) + ((lane >> 3) & 1) * 8;
                int seg = ks * 2 + (lane >> 4);
                ldsm_x4(a[mi][0], a[mi][1], a[mi][2], a[mi][3],
                        baseA + (uint32_t)(row * SROW + seg * 4) * 4u);
            }
#pragma unroll
            for (int p = 0; p < 4; p++) {
                int nf = p * 2;
                int col = wn + (nf + (lane >> 4)) * 8 + (lane & 7);
                int segl = ks * 2 + ((lane >> 3) & 1);
                int seg = segl ^ ((col >> 3) & 3);
                ldsm_x4(b[nf][0], b[nf][1], b[nf + 1][0], b[nf + 1][1],
                        baseB + (uint32_t)(col * SROW + seg * 4) * 4u);
            }
#pragma unroll
            for (int mi = 0; mi < 2; mi++)
#pragma unroll
                for (int nf = 0; nf < 8; nf++) {
                    asm volatile(
                        "mma.sync.aligned.m16n8k16.row.col.f32.bf16.bf16.f32 "
                        "{%0,%1,%2,%3}, {%4,%5,%6,%7}, {%8,%9}, {%0,%1,%2,%3};"
                        : "+f"(c[mi][nf][0]), "+f"(c[mi][nf][1]),
                          "+f"(c[mi][nf][2]), "+f"(c[mi][nf][3])
                        : "r"(a[mi][0]), "r"(a[mi][1]), "r"(a[mi][2]), "r"(a[mi][3]),
                          "r"(b[nf][0]), "r"(b[nf][1]));
                }
        }
        if (nxt) {
            store_smem(buf ^ 1);
            __syncthreads();
            buf ^= 1;
        }
    }

#pragma unroll
    for (int mi = 0; mi < 2; mi++) {
        int row0 = brow + wm + mi * 16 + g;
#pragma unroll
        for (int nf = 0; nf < 8; nf++) {
            int col = bcol + wn + nf * 8 + 2 * t;
            float v0 = c[mi][nf][0], v1 = c[mi][nf][1];
            float v2 = c[mi][nf][2], v3 = c[mi][nf][3];
            if (RELU) {
                v0 = fmaxf(v0, 0.f); v1 = fmaxf(v1, 0.f);
                v2 = fmaxf(v2, 0.f); v3 = fmaxf(v3, 0.f);
            }
            if (sizeof(OutT) == 4) {
                float* Cf = (float*)C;
                if (row0 < M)
                    *(float2*)(Cf + (size_t)row0 * N + col) = make_float2(v0, v1);
                if (row0 + 8 < M)
                    *(float2*)(Cf + (size_t)(row0 + 8) * N + col) = make_float2(v2, v3);
            } else {
                __nv_bfloat16* Cb = (__nv_bfloat16*)C;
                if (row0 < M)
                    *(uint32_t*)(Cb + (size_t)row0 * N + col) = bfpair(v0, v1);
                if (row0 + 8 < M)
                    *(uint32_t*)(Cb + (size_t)(row0 + 8) * N + col) = bfpair(v2, v3);
            }
        }
    }
}

// ---------------- pack Wl|Wr -> g_Wlr [K][2*dout] bf16 ----------------
__global__ void k_packW(const float* __restrict__ Wl, const float* __restrict__ Wr,
                        int K, int dout) {
    int idx = blockIdx.x * blockDim.x + threadIdx.x;
    int tot = K * 2 * dout / 4;
    if (idx >= tot) return;
    int k = idx / (2 * dout / 4), c4 = idx % (2 * dout / 4);
    int c = c4 * 4;
    float4 v = (c < dout) ? *(const float4*)(Wl + (size_t)k * dout + c)
                          : *(const float4*)(Wr + (size_t)k * dout + c - dout);
    uint2 o = make_uint2(bfpair(v.x, v.y), bfpair(v.z, v.w));
    *(uint2*)(g_Wlr + (size_t)k * 2 * dout + c) = o;
}

// ---------------- fused GAT layer: alpha + online softmax + aggregation (warp/node) ------
template <int NC>   // NC = dout/32
__global__ __launch_bounds__(256) void k_gat(
        const int* __restrict__ src, const float* __restrict__ ea,
        const float* __restrict__ We, const float* __restrict__ att,
        const float* __restrict__ bias, __nv_bfloat16* __restrict__ hn, int dorelu) {
    const int dout = NC * 32;
    __shared__ float sWe[ED][NC * 32];
    __shared__ float sAtt[NC * 32];
    __shared__ float sB[NC * 32];
    int tid = threadIdx.x;
    for (int i = tid; i < ED * dout; i += 256) sWe[i / dout][i % dout] = We[i];
    for (int i = tid; i < dout; i += 256) { sAtt[i] = att[i]; sB[i] = bias[i]; }
    __syncthreads();

    int lane = tid & 31, w = tid >> 5;
    int n = blockIdx.x * 8 + w;
    if (n >= NN) return;

    const float* xrp = g_xlr + (size_t)n * 2 * dout + dout;
    float xrv[NC];
#pragma unroll
    for (int q = 0; q < NC; q++) xrv[q] = xrp[q * 32 + lane];

    float m = -1e30f, ssum = 0.0f;
    float acc[NC];
#pragma unroll
    for (int q = 0; q < NC; q++) acc[q] = 0.0f;

    int beg = g_off[n], end = g_off[n + 1];
    for (int i = beg; i < end; i++) {
        int e = g_eid[i];
        int s;
        const float* eap;
        if (e < EE) { s = src[e]; eap = ea + (size_t)e * ED; }
        else        { s = e - EE; eap = g_mean + (size_t)s * ED; }
        float eareg = (lane < ED) ? eap[lane] : 0.0f;
        const float* xlp = g_xlr + (size_t)s * 2 * dout;
        float xv[NC];
#pragma unroll
        for (int q = 0; q < NC; q++) xv[q] = xlp[q * 32 + lane];
        float ed[NC];
#pragma unroll
        for (int q = 0; q < NC; q++) ed[q] = 0.0f;
#pragma unroll
        for (int j = 0; j < ED; j++) {
            float aj = __shfl_sync(0xffffffffu, eareg, j);
#pragma unroll
            for (int q = 0; q < NC; q++) ed[q] += aj * sWe[j][q * 32 + lane];
        }
        float p = 0.0f;
#pragma unroll
        for (int q = 0; q < NC; q++) {
            float v = xv[q] + xrv[q] + ed[q];
            v = v > 0.0f ? v : 0.2f * v;
            p += sAtt[q * 32 + lane] * v;
        }
#pragma unroll
        for (int o = 16; o; o >>= 1) p += __shfl_xor_sync(0xffffffffu, p, o);
        // online softmax update
        float nm = fmaxf(m, p);
        float cs = expf(m - nm);
        float ex = expf(p - nm);
        ssum = ssum * cs + ex;
#pragma unroll
        for (int q = 0; q < NC; q++) acc[q] = acc[q] * cs + ex * xv[q];
        m = nm;
    }
    float inv = 1.0f / fmaxf(ssum, 1e-16f);
    __nv_bfloat16* hp = hn + (size_t)n * dout;
#pragma unroll
    for (int q = 0; q < NC; q++) {
        float v = acc[q] * inv + sB[q * 32 + lane];
        hp[q * 32 + lane] = __float2bfloat16(dorelu ? fmaxf(v, 0.0f) : v);
    }
}

// ---------------- pack Wbi[k,i,j] -> g_UV[i][U(c) | V(c)] bf16 ----------------
__global__ void k_pack(const float* __restrict__ Wbi) {
    int idx = blockIdx.x * blockDim.x + threadIdx.x;
    const int tot = HMAX * CB2 / 4;
    if (idx >= tot) return;
    int i = idx / (CB2 / 4), c4 = idx % (CB2 / 4);
    int c = c4 * 4;
    int isV = (c >= CBI);
    int cc = c - isV * CBI;
    int k = cc >> 4, j = cc & 15;
    float4 v = *(const float4*)(Wbi + ((size_t)k * 1024 + isV * 512 + i) * 16 + j);
    uint2 o = make_uint2(bfpair(v.x, v.y), bfpair(v.z, v.w));
    *(uint2*)(g_UV + (size_t)i * CB2 + c) = o;
}

// ---------------- pad Wm1 into [KP][NP] bf16 with bias row ----------------
__global__ void k_packM1(const float* __restrict__ Wm1, const float* __restrict__ bm1) {
    int idx = blockIdx.x * blockDim.x + threadIdx.x;
    if (idx >= KP * NP) return;
    int r = idx / NP, c = idx % NP;
    float v = 0.0f;
    if (c < KBI) {
        if (r < KBI) v = Wm1[(size_t)r * KBI + c];
        else if (r == KBI) v = bm1[c];
    }
    g_Wm1p[idx] = __float2bfloat16(v);
}

// ---------------- bilinear: bi[e][k] = sum_j (A[src]+B[dst])[k*16+j]*ea[j] + bbi[k] -------
__global__ void k_bilin(const int* __restrict__ src, const int* __restrict__ dst,
                        const float* __restrict__ ea, const float* __restrict__ bbi) {
    int tid = threadIdx.x, w = tid >> 5, lane = tid & 31;
    int e = blockIdx.x * 8 + w;
    if (e >= EE) return;
    int s = src[e], d = dst[e];
    int j4 = lane & 3, kk = lane >> 2;
    float4 eav = *(const float4*)(ea + (size_t)e * ED + j4 * 4);
    const __nv_bfloat16* Ap = g_ABb + (size_t)s * CB2;
    const __nv_bfloat16* Bp = g_ABb + (size_t)d * CB2 + CBI;
    __nv_bfloat16* bo = g_bib + (size_t)e * KP;
#pragma unroll 4
    for (int it = 0; it < 34; it++) {
        int base = (it * 8 + kk) * 16 + j4 * 4;
        float2 a01 = __bfloat1622float2(*(const __nv_bfloat162*)(Ap + base));
        float2 a23 = __bfloat1622float2(*(const __nv_bfloat162*)(Ap + base + 2));
        float2 b01 = __bfloat1622float2(*(const __nv_bfloat162*)(Bp + base));
        float2 b23 = __bfloat1622float2(*(const __nv_bfloat162*)(Bp + base + 2));
        float v = (a01.x + b01.x) * eav.x + (a01.y + b01.y) * eav.y
                + (a23.x + b23.x) * eav.z + (a23.y + b23.y) * eav.w;
        v += __shfl_xor_sync(0xffffffffu, v, 1);
        v += __shfl_xor_sync(0xffffffffu, v, 2);
        if (j4 == 0) {
            int k = it * 8 + kk;
            bo[k] = __float2bfloat16(v + bbi[k]);
        }
    }
    if (lane < KP - KBI)
        bo[KBI + lane] = __float2bfloat16(lane == 0 ? 1.0f : 0.0f);
}

// ---------------- tail: m2 = relu(m1@Wm2+bm2); out = sigmoid(m2@Wm3+bm3) ------------------
__global__ void k_tail(const float* __restrict__ Wm2, const float* __restrict__ bm2,
                       const float* __restrict__ Wm3, const float* __restrict__ bm3,
                       float* __restrict__ out) {
    int tid = threadIdx.x, w = tid >> 5, lane = tid & 31;
    int e = blockIdx.x * 8 + w;
    if (e >= EE) return;
    const float* m1p = g_m1 + (size_t)e * NP;
    float acc = bm2[lane];
    for (int k0 = 0; k0 < KBI; k0 += 32) {
        float mv = m1p[k0 + lane];
        int jmax = (KBI - k0 < 32) ? (KBI - k0) : 32;
        for (int j = 0; j < jmax; j++) {
            float m = __shfl_sync(0xffffffffu, mv, j);
            acc += m * Wm2[(size_t)(k0 + j) * 32 + lane];
        }
    }
    float m2v = fmaxf(acc, 0.0f);
    float p = m2v * Wm3[lane];
#pragma unroll
    for (int o = 16; o; o >>= 1) p += __shfl_xor_sync(0xffffffffu, p, o);
    if (lane == 0) out[e] = 1.0f / (1.0f + expf(-(p + bm3[0])));
}

// ---------------- host ----------------
static inline dim3 gemm_grid(int M, int Nn) { return dim3(Nn / 128, (M + 127) / 128); }

extern "C" void kernel_launch(void* const* d_in, const int* in_sizes, int n_in,
                              void* d_out, int out_size) {
    const float* x         = (const float*)d_in[0];
    const float* edge_attr = (const float*)d_in[1];
    const int*   eidx      = (const int*)d_in[2];
    const int* src = eidx;
    const int* dst = eidx + EE;
    const float *Wl[4], *Wr[4], *We[4], *att[4], *bb[4];
    for (int l = 0; l < 4; l++) {
        int base = 3 + l * 5;
        Wl[l]  = (const float*)d_in[base + 0];
        Wr[l]  = (const float*)d_in[base + 1];
        We[l]  = (const float*)d_in[base + 2];
        att[l] = (const float*)d_in[base + 3];
        bb[l]  = (const float*)d_in[base + 4];
    }
    const float* Wbi = (const float*)d_in[23];
    const float* bbi = (const float*)d_in[24];
    const float* Wm1 = (const float*)d_in[25];
    const float* bm1 = (const float*)d_in[26];
    const float* Wm2 = (const float*)d_in[27];
    const float* bm2 = (const float*)d_in[28];
    const float* Wm3 = (const float*)d_in[29];
    const float* bm3 = (const float*)d_in[30];
    float* out = (float*)d_out;

    // scratch pointers
    float *xlr, *cnt, *msum, *m1;
    __nv_bfloat16 *xb, *h1, *h2, *Wlr, *UV, *ABb, *bib, *Wm1p;
    int *deg, *pos;
    cudaGetSymbolAddress((void**)&xb, g_xb);
    cudaGetSymbolAddress((void**)&h1, g_h1);
    cudaGetSymbolAddress((void**)&h2, g_h2);
    cudaGetSymbolAddress((void**)&xlr, g_xlr);
    cudaGetSymbolAddress((void**)&Wlr, g_Wlr);
    cudaGetSymbolAddress((void**)&UV, g_UV);
    cudaGetSymbolAddress((void**)&ABb, g_ABb);
    cudaGetSymbolAddress((void**)&cnt, g_cnt);
    cudaGetSymbolAddress((void**)&msum, g_msum);
    cudaGetSymbolAddress((void**)&deg, g_deg);
    cudaGetSymbolAddress((void**)&pos, g_pos);
    cudaGetSymbolAddress((void**)&bib, g_bib);
    cudaGetSymbolAddress((void**)&m1, g_m1);
    cudaGetSymbolAddress((void**)&Wm1p, g_Wm1p);

    // edge_attr mean for self loops
    cudaMemsetAsync(cnt, 0, NN * sizeof(float));
    cudaMemsetAsync(msum, 0, NN * ED * sizeof(float));
    k_count<<<(EE * ED + 255) / 256, 256>>>(dst, edge_attr);
    k_mean<<<(NN * ED + 255) / 256, 256>>>();

    // CSR build (augmented graph, keyed by dst)
    cudaMemsetAsync(deg, 0, NN * sizeof(int));
    cudaMemsetAsync(pos, 0, NN * sizeof(int));
    k_deg<<<(EA + 255) / 256, 256>>>(dst);
    k_scan<<<1, 1024>>>();
    k_fill<<<(EA + 255) / 256, 256>>>(dst);

    // x -> bf16
    k_cvtx<<<(NN * 32 / 2 + 255) / 256, 256>>>(x);

    const __nv_bfloat16* hcur = xb;
    int din = 32;
    __nv_bfloat16* hbufs[2] = { h1, h2 };

    for (int l = 0; l < 4; l++) {
        int dout = (l == 0) ? 256 : 512;
        k_packW<<<(din * 2 * dout / 4 + 255) / 256, 256>>>(Wl[l], Wr[l], din, dout);
        bf16gemm<float, false><<<gemm_grid(NN, 2 * dout), 256>>>(hcur, Wlr, xlr, NN, 2 * dout, din);
        __nv_bfloat16* hn = hbufs[l & 1];
        int dorelu = (l < 3) ? 1 : 0;
        if (dout == 256)
            k_gat<8><<<(NN + 7) / 8, 256>>>(src, edge_attr, We[l], att[l], bb[l], hn, dorelu);
        else
            k_gat<16><<<(NN + 7) / 8, 256>>>(src, edge_attr, We[l], att[l], bb[l], hn, dorelu);
        hcur = hn;
        din = dout;
    }

    // edge scoring
    k_pack<<<(HMAX * CB2 / 4 + 255) / 256, 256>>>(Wbi);
    bf16gemm<__nv_bfloat16, false><<<gemm_grid(NN, CB2), 256>>>(hcur, UV, ABb, NN, CB2, HMAX);
    k_packM1<<<(KP * NP + 255) / 256, 256>>>(Wm1, bm1);
    k_bilin<<<(EE + 7) / 8, 256>>>(src, dst, edge_attr, bbi);
    bf16gemm<float, true><<<gemm_grid(EE, NP), 256>>>(bib, Wm1p, m1, EE, NP, KP);
    k_tail<<<(EE + 7) / 8, 256>>>(Wm2, bm2, Wm3, bm3, out);
}

// round 13
// speedup vs baseline: 1.6292x; 1.6292x over previous
#include <cuda_runtime.h>
#include <cuda_bf16.h>
#include <math.h>
#include <stdint.h>

#define NN 10000
#define EE 50000
#define EA 60000      // E + N self loops
#define ED 16
#define KBI 272
#define CBI 4352      // 272*16
#define CB2 8704      // 2*CBI
#define HMAX 512
#define KP 288        // KBI padded (bias row at 272), %32 == 0
#define NP 384        // KBI padded to N%128

// ---------------- scratch (static device globals; no runtime alloc) ----------------
__device__ __nv_bfloat16 g_xb[NN * 32];             // x converted to bf16
__device__ __nv_bfloat16 g_h1[NN * HMAX];
__device__ __nv_bfloat16 g_h2[NN * HMAX];
__device__ float g_xlr[NN * 1024];                  // [node][xl(dout) | xr(dout)]
__device__ float g_cnt[NN];
__device__ float g_msum[NN * ED];
__device__ float g_mean[NN * ED];
__device__ int   g_deg[NN];
__device__ int   g_off[NN + 1];
__device__ int   g_pos[NN];
__device__ int   g_eid[EA];
__device__ __nv_bfloat16 g_Wlrt[1024 * HMAX];       // TRANSPOSED [c(2*dout)][k] bf16
__device__ __nv_bfloat16 g_UVt[(size_t)CB2 * HMAX]; // TRANSPOSED [c][i] bf16
__device__ __nv_bfloat16 g_ABb[(size_t)NN * CB2];   // per-node factors, bf16
__device__ __nv_bfloat16 g_bib[(size_t)EE * KP];    // bilinear output + bias col, bf16
__device__ float g_m1[(size_t)EE * NP];             // relu(bi@Wm1+bm1)
__device__ __nv_bfloat16 g_Wm1pt[NP * KP];          // TRANSPOSED padded Wm1 [o][r] bf16

// ---------------- helpers ----------------
__device__ __forceinline__ uint32_t bfpair(float lo, float hi) {
    __nv_bfloat162 h2 = __floats2bfloat162_rn(lo, hi);
    return *reinterpret_cast<uint32_t*>(&h2);
}
__device__ __forceinline__ void ldsm_x4(uint32_t& r0, uint32_t& r1, uint32_t& r2,
                                        uint32_t& r3, uint32_t addr) {
    asm volatile("ldmatrix.sync.aligned.m8n8.x4.shared.b16 {%0,%1,%2,%3}, [%4];"
                 : "=r"(r0), "=r"(r1), "=r"(r2), "=r"(r3) : "r"(addr));
}
__device__ __forceinline__ void cpa16(uint32_t dst, const void* src, int sz) {
    asm volatile("cp.async.cg.shared.global [%0], [%1], 16, %2;"
                 :: "r"(dst), "l"(src), "r"(sz) : "memory");
}

// ---------------- edge_attr mean per dst (self-loop fill 'mean') ----------------
__global__ void k_count(const int* __restrict__ dst, const float* __restrict__ ea) {
    int idx = blockIdx.x * blockDim.x + threadIdx.x;
    if (idx >= EE * ED) return;
    int e = idx >> 4, j = idx & 15;
    int d = dst[e];
    atomicAdd(&g_msum[d * ED + j], ea[idx]);
    if (j == 0) atomicAdd(&g_cnt[d], 1.0f);
}
__global__ void k_mean() {
    int idx = blockIdx.x * blockDim.x + threadIdx.x;
    if (idx >= NN * ED) return;
    g_mean[idx] = g_msum[idx] / fmaxf(g_cnt[idx >> 4], 1.0f);
}

// ---------------- CSR build over augmented edges (dst = sort key) ----------------
__global__ void k_deg(const int* __restrict__ dst) {
    int e = blockIdx.x * blockDim.x + threadIdx.x;
    if (e >= EA) return;
    int d = (e < EE) ? dst[e] : (e - EE);
    atomicAdd(&g_deg[d], 1);
}
__global__ void k_scan() {
    __shared__ int wsum[32];
    int tid = threadIdx.x, lane = tid & 31, w = tid >> 5;
    int base = 0;
    for (int start = 0; start < NN; start += 1024) {
        int i = start + tid;
        int x = (i < NN) ? g_deg[i] : 0;
#pragma unroll
        for (int o = 1; o < 32; o <<= 1) {
            int t = __shfl_up_sync(0xffffffffu, x, o);
            if (lane >= o) x += t;
        }
        if (lane == 31) wsum[w] = x;
        __syncthreads();
        if (w == 0) {
            int s = wsum[lane];
#pragma unroll
            for (int o = 1; o < 32; o <<= 1) {
                int t = __shfl_up_sync(0xffffffffu, s, o);
                if (lane >= o) s += t;
            }
            wsum[lane] = s;
        }
        __syncthreads();
        int off = (w > 0) ? wsum[w - 1] : 0;
        if (i < NN) g_off[i + 1] = base + off + x;
        base += wsum[31];
        __syncthreads();
    }
    if (tid == 0) g_off[0] = 0;
}
__global__ void k_fill(const int* __restrict__ dst) {
    int e = blockIdx.x * blockDim.x + threadIdx.x;
    if (e >= EA) return;
    int d = (e < EE) ? dst[e] : (e - EE);
    int p = atomicAdd(&g_pos[d], 1);
    g_eid[g_off[d] + p] = e;
}

// ---------------- x -> bf16 ----------------
__global__ void k_cvtx(const float* __restrict__ x) {
    int idx = blockIdx.x * blockDim.x + threadIdx.x;
    if (idx >= NN * 32 / 2) return;
    float2 v = *(const float2*)(x + idx * 2);
    *(uint32_t*)(g_xb + idx * 2) = bfpair(v.x, v.y);
}

// ------- BF16 mma.sync GEMM v2: C[M,N] = A[M,K] * Bt[N,K]^T, bf16 operands --------------
// Both operands K-major. cp.async 3-stage pipeline, ldmatrix fragments.
// BM=BN=128, BK=32, 256 threads = 8 warps (4 in M x 2 in N), warp tile 32x64.
// Requires: N % 128 == 0, K % 32 == 0. M arbitrary (guarded, zero-filled).
#define SROW 20
#define GBUF (128 * SROW * 4)      // 10240 B per operand per stage
#define GSMEM (6 * GBUF)           // 3 stages x 2 operands = 61440 B
template <typename OutT, bool RELU>
__global__ __launch_bounds__(256) void bf16gemm(
        const __nv_bfloat16* __restrict__ A, const __nv_bfloat16* __restrict__ Bt,
        OutT* __restrict__ C, int M, int N, int K) {
    extern __shared__ char dynsm[];
    uint32_t smA;
    {
        uint64_t a64 = (uint64_t)__cvta_generic_to_shared(dynsm);
        smA = (uint32_t)a64;
    }
    const uint32_t smB0 = smA + 3 * GBUF;

    int tid = threadIdx.x;
    int lane = tid & 31, wid = tid >> 5;
    int g = lane >> 2, t = lane & 3;
    int wm = (wid & 3) * 32;
    int wn = (wid >> 2) * 64;
    int brow = blockIdx.y * 128;
    int bcol = blockIdx.x * 128;

    float c[2][8][4];
#pragma unroll
    for (int mi = 0; mi < 2; mi++)
#pragma unroll
        for (int nf = 0; nf < 8; nf++)
#pragma unroll
            for (int q = 0; q < 4; q++) c[mi][nf][q] = 0.0f;

    // staging: thread covers row tid>>1, kpair half (tid&1)*8 (16 bf16 = 32B = 2x16B)
    int arow = tid >> 1;
    int ahalf = tid & 1;
    bool a_ok = (brow + arow) < M;
    const __nv_bfloat16* Aip = A + (size_t)(brow + arow) * K + ahalf * 16;
    const __nv_bfloat16* Bip = Bt + (size_t)(bcol + arow) * K + ahalf * 16;
    uint32_t soff = (uint32_t)(arow * SROW + ahalf * 8) * 4u;
    int asz = a_ok ? 16 : 0;

    int nslab = K >> 5;
    auto issue = [&](int s) {
        int buf = s % 3;
        int k0 = s << 5;
        uint32_t da = smA + buf * GBUF + soff;
        uint32_t db = smB0 + buf * GBUF + soff;
        cpa16(da, Aip + k0, asz);
        cpa16(da + 16, Aip + k0 + 8, asz);
        cpa16(db, Bip + k0, 16);
        cpa16(db + 16, Bip + k0 + 8, 16);
        asm volatile("cp.async.commit_group;" ::: "memory");
    };

    issue(0);
    if (nslab > 1) issue(1);

    for (int s = 0; s < nslab; s++) {
        if (s + 1 < nslab)
            asm volatile("cp.async.wait_group 1;" ::: "memory");
        else
            asm volatile("cp.async.wait_group 0;" ::: "memory");
        __syncthreads();
        int buf = s % 3;
        uint32_t baseA = smA + buf * GBUF;
        uint32_t baseB = smB0 + buf * GBUF;
#pragma unroll
        for (int ks = 0; ks < 2; ks++) {
            uint32_t a[2][4], b[8][2];
#pragma unroll
            for (int mi = 0; mi < 2; mi++) {
                int row = wm + mi * 16 + (lane & 7) + ((lane >> 3) & 1) * 8;
                int seg = ks * 2 + (lane >> 4);
                ldsm_x4(a[mi][0], a[mi][1], a[mi][2], a[mi][3],
                        baseA + (uint32_t)(row * SROW + seg * 4) * 4u);
            }
#pragma unroll
            for (int p = 0; p < 4; p++) {
                int nf = p * 2;
                int col = wn + (nf + (lane >> 4)) * 8 + (lane & 7);
                int seg = ks * 2 + ((lane >> 3) & 1);
                ldsm_x4(b[nf][0], b[nf][1], b[nf + 1][0], b[nf + 1][1],
                        baseB + (uint32_t)(col * SROW + seg * 4) * 4u);
            }
#pragma unroll
            for (int mi = 0; mi < 2; mi++)
#pragma unroll
                for (int nf = 0; nf < 8; nf++) {
                    asm volatile(
                        "mma.sync.aligned.m16n8k16.row.col.f32.bf16.bf16.f32 "
                        "{%0,%1,%2,%3}, {%4,%5,%6,%7}, {%8,%9}, {%0,%1,%2,%3};"
                        : "+f"(c[mi][nf][0]), "+f"(c[mi][nf][1]),
                          "+f"(c[mi][nf][2]), "+f"(c[mi][nf][3])
                        : "r"(a[mi][0]), "r"(a[mi][1]), "r"(a[mi][2]), "r"(a[mi][3]),
                          "r"(b[nf][0]), "r"(b[nf][1]));
                }
        }
        if (s + 2 < nslab) issue(s + 2);
    }

#pragma unroll
    for (int mi = 0; mi < 2; mi++) {
        int row0 = brow + wm + mi * 16 + g;
#pragma unroll
        for (int nf = 0; nf < 8; nf++) {
            int col = bcol + wn + nf * 8 + 2 * t;
            float v0 = c[mi][nf][0], v1 = c[mi][nf][1];
            float v2 = c[mi][nf][2], v3 = c[mi][nf][3];
            if (RELU) {
                v0 = fmaxf(v0, 0.f); v1 = fmaxf(v1, 0.f);
                v2 = fmaxf(v2, 0.f); v3 = fmaxf(v3, 0.f);
            }
            if (sizeof(OutT) == 4) {
                float* Cf = (float*)C;
                if (row0 < M)
                    *(float2*)(Cf + (size_t)row0 * N + col) = make_float2(v0, v1);
                if (row0 + 8 < M)
                    *(float2*)(Cf + (size_t)(row0 + 8) * N + col) = make_float2(v2, v3);
            } else {
                __nv_bfloat16* Cb = (__nv_bfloat16*)C;
                if (row0 < M)
                    *(uint32_t*)(Cb + (size_t)row0 * N + col) = bfpair(v0, v1);
                if (row0 + 8 < M)
                    *(uint32_t*)(Cb + (size_t)(row0 + 8) * N + col) = bfpair(v2, v3);
            }
        }
    }
}

// ------- pack Wl|Wr TRANSPOSED -> g_Wlrt[c][k], c in [0,2*dout), 32x32 smem tiles --------
__global__ void k_packWt(const float* __restrict__ Wl, const float* __restrict__ Wr,
                         int K, int dout) {
    __shared__ float tile[32][33];
    int kb = blockIdx.x * 32, cb = blockIdx.y * 32;
    int tx = threadIdx.x, ty = threadIdx.y;   // 32x8
    const float* W = (cb < dout) ? Wl : Wr;
    int csrc = (cb < dout) ? cb : cb - dout;
    for (int i = ty; i < 32; i += 8)
        tile[i][tx] = W[(size_t)(kb + i) * dout + csrc + tx];
    __syncthreads();
    for (int i = ty; i < 32; i += 8)
        g_Wlrt[(size_t)(cb + i) * K + kb + tx] = __float2bfloat16(tile[tx][i]);
}

// ---------------- fused GAT layer: alpha + online softmax + aggregation (warp/node) ------
template <int NC>   // NC = dout/32
__global__ __launch_bounds__(256) void k_gat(
        const int* __restrict__ src, const float* __restrict__ ea,
        const float* __restrict__ We, const float* __restrict__ att,
        const float* __restrict__ bias, __nv_bfloat16* __restrict__ hn, int dorelu) {
    const int dout = NC * 32;
    __shared__ float sWe[ED][NC * 32];
    __shared__ float sAtt[NC * 32];
    __shared__ float sB[NC * 32];
    int tid = threadIdx.x;
    for (int i = tid; i < ED * dout; i += 256) sWe[i / dout][i % dout] = We[i];
    for (int i = tid; i < dout; i += 256) { sAtt[i] = att[i]; sB[i] = bias[i]; }
    __syncthreads();

    int lane = tid & 31, w = tid >> 5;
    int n = blockIdx.x * 8 + w;
    if (n >= NN) return;

    const float* xrp = g_xlr + (size_t)n * 2 * dout + dout;
    float xrv[NC];
#pragma unroll
    for (int q = 0; q < NC; q++) xrv[q] = xrp[q * 32 + lane];

    float m = -1e30f, ssum = 0.0f;
    float acc[NC];
#pragma unroll
    for (int q = 0; q < NC; q++) acc[q] = 0.0f;

    int beg = g_off[n], end = g_off[n + 1];
    for (int i = beg; i < end; i++) {
        int e = g_eid[i];
        int s;
        const float* eap;
        if (e < EE) { s = src[e]; eap = ea + (size_t)e * ED; }
        else        { s = e - EE; eap = g_mean + (size_t)s * ED; }
        float eareg = (lane < ED) ? eap[lane] : 0.0f;
        const float* xlp = g_xlr + (size_t)s * 2 * dout;
        float xv[NC];
#pragma unroll
        for (int q = 0; q < NC; q++) xv[q] = xlp[q * 32 + lane];
        float ed[NC];
#pragma unroll
        for (int q = 0; q < NC; q++) ed[q] = 0.0f;
#pragma unroll
        for (int j = 0; j < ED; j++) {
            float aj = __shfl_sync(0xffffffffu, eareg, j);
#pragma unroll
            for (int q = 0; q < NC; q++) ed[q] += aj * sWe[j][q * 32 + lane];
        }
        float p = 0.0f;
#pragma unroll
        for (int q = 0; q < NC; q++) {
            float v = xv[q] + xrv[q] + ed[q];
            v = v > 0.0f ? v : 0.2f * v;
            p += sAtt[q * 32 + lane] * v;
        }
#pragma unroll
        for (int o = 16; o; o >>= 1) p += __shfl_xor_sync(0xffffffffu, p, o);
        float nm = fmaxf(m, p);
        float cs = expf(m - nm);
        float ex = expf(p - nm);
        ssum = ssum * cs + ex;
#pragma unroll
        for (int q = 0; q < NC; q++) acc[q] = acc[q] * cs + ex * xv[q];
        m = nm;
    }
    float inv = 1.0f / fmaxf(ssum, 1e-16f);
    __nv_bfloat16* hp = hn + (size_t)n * dout;
#pragma unroll
    for (int q = 0; q < NC; q++) {
        float v = acc[q] * inv + sB[q * 32 + lane];
        hp[q * 32 + lane] = __float2bfloat16(dorelu ? fmaxf(v, 0.0f) : v);
    }
}

// ---- pack Wbi[k,i,j] -> TRANSPOSED g_UVt[isV*CBI + k*16 + j][i], bf16, smem transpose ----
__global__ void k_packT(const float* __restrict__ Wbi) {
    __shared__ __nv_bfloat16 sb[512 * 17];
    int k = blockIdx.x, isV = blockIdx.y, tid = threadIdx.x;
    const float* src = Wbi + ((size_t)k * 1024 + isV * 512) * 16;
#pragma unroll
    for (int q = 0; q < 8; q++) {
        int idx = tid + q * 256;               // 0..2047 float4s over [i(512)][j(16)]
        float4 v = ((const float4*)src)[idx];
        int i = idx >> 2, j4 = (idx & 3) * 4;
        sb[i * 17 + j4 + 0] = __float2bfloat16(v.x);
        sb[i * 17 + j4 + 1] = __float2bfloat16(v.y);
        sb[i * 17 + j4 + 2] = __float2bfloat16(v.z);
        sb[i * 17 + j4 + 3] = __float2bfloat16(v.w);
    }
    __syncthreads();
#pragma unroll
    for (int q = 0; q < 16; q++) {
        int idx = tid + q * 256;               // 0..4095 uint32s: [j(16)][ipair(256)]
        int j = idx >> 8, ip = idx & 255, i0 = ip * 2;
        __nv_bfloat162 h2 = __halves2bfloat162(sb[i0 * 17 + j], sb[(i0 + 1) * 17 + j]);
        *(uint32_t*)(g_UVt + ((size_t)(isV * CBI + k * 16 + j)) * HMAX + i0) =
            *reinterpret_cast<uint32_t*>(&h2);
    }
}

// ---------------- pad Wm1 TRANSPOSED into [NP][KP] bf16 with bias row ----------------
__global__ void k_packM1t(const float* __restrict__ Wm1, const float* __restrict__ bm1) {
    int idx = blockIdx.x * blockDim.x + threadIdx.x;
    if (idx >= NP * KP) return;
    int o = idx / KP, r = idx % KP;
    float v = 0.0f;
    if (o < KBI) {
        if (r < KBI) v = Wm1[(size_t)r * KBI + o];
        else if (r == KBI) v = bm1[o];
    }
    g_Wm1pt[idx] = __float2bfloat16(v);
}

// ---------------- bilinear: bi[e][k] = sum_j (A[src]+B[dst])[k*16+j]*ea[j] + bbi[k] -------
__global__ void k_bilin(const int* __restrict__ src, const int* __restrict__ dst,
                        const float* __restrict__ ea, const float* __restrict__ bbi) {
    int tid = threadIdx.x, w = tid >> 5, lane = tid & 31;
    int e = blockIdx.x * 8 + w;
    if (e >= EE) return;
    int s = src[e], d = dst[e];
    int j4 = lane & 3, kk = lane >> 2;
    float4 eav = *(const float4*)(ea + (size_t)e * ED + j4 * 4);
    const __nv_bfloat16* Ap = g_ABb + (size_t)s * CB2;
    const __nv_bfloat16* Bp = g_ABb + (size_t)d * CB2 + CBI;
    __nv_bfloat16* bo = g_bib + (size_t)e * KP;
#pragma unroll 4
    for (int it = 0; it < 34; it++) {
        int base = (it * 8 + kk) * 16 + j4 * 4;
        float2 a01 = __bfloat1622float2(*(const __nv_bfloat162*)(Ap + base));
        float2 a23 = __bfloat1622float2(*(const __nv_bfloat162*)(Ap + base + 2));
        float2 b01 = __bfloat1622float2(*(const __nv_bfloat162*)(Bp + base));
        float2 b23 = __bfloat1622float2(*(const __nv_bfloat162*)(Bp + base + 2));
        float v = (a01.x + b01.x) * eav.x + (a01.y + b01.y) * eav.y
                + (a23.x + b23.x) * eav.z + (a23.y + b23.y) * eav.w;
        v += __shfl_xor_sync(0xffffffffu, v, 1);
        v += __shfl_xor_sync(0xffffffffu, v, 2);
        if (j4 == 0) {
            int k = it * 8 + kk;
            bo[k] = __float2bfloat16(v + bbi[k]);
        }
    }
    if (lane < KP - KBI)
        bo[KBI + lane] = __float2bfloat16(lane == 0 ? 1.0f : 0.0f);
}

// ---------------- tail: m2 = relu(m1@Wm2+bm2); out = sigmoid(m2@Wm3+bm3) ------------------
__global__ void k_tail(const float* __restrict__ Wm2, const float* __restrict__ bm2,
                       const float* __restrict__ Wm3, const float* __restrict__ bm3,
                       float* __restrict__ out) {
    int tid = threadIdx.x, w = tid >> 5, lane = tid & 31;
    int e = blockIdx.x * 8 + w;
    if (e >= EE) return;
    const float* m1p = g_m1 + (size_t)e * NP;
    float acc = bm2[lane];
    for (int k0 = 0; k0 < KBI; k0 += 32) {
        float mv = m1p[k0 + lane];
        int jmax = (KBI - k0 < 32) ? (KBI - k0) : 32;
        for (int j = 0; j < jmax; j++) {
            float m = __shfl_sync(0xffffffffu, mv, j);
            acc += m * Wm2[(size_t)(k0 + j) * 32 + lane];
        }
    }
    float m2v = fmaxf(acc, 0.0f);
    float p = m2v * Wm3[lane];
#pragma unroll
    for (int o = 16; o; o >>= 1) p += __shfl_xor_sync(0xffffffffu, p, o);
    if (lane == 0) out[e] = 1.0f / (1.0f + expf(-(p + bm3[0])));
}

// ---------------- host ----------------
static inline dim3 gemm_grid(int M, int Nn) { return dim3(Nn / 128, (M + 127) / 128); }

extern "C" void kernel_launch(void* const* d_in, const int* in_sizes, int n_in,
                              void* d_out, int out_size) {
    const float* x         = (const float*)d_in[0];
    const float* edge_attr = (const float*)d_in[1];
    const int*   eidx      = (const int*)d_in[2];
    const int* src = eidx;
    const int* dst = eidx + EE;
    const float *Wl[4], *Wr[4], *We[4], *att[4], *bb[4];
    for (int l = 0; l < 4; l++) {
        int base = 3 + l * 5;
        Wl[l]  = (const float*)d_in[base + 0];
        Wr[l]  = (const float*)d_in[base + 1];
        We[l]  = (const float*)d_in[base + 2];
        att[l] = (const float*)d_in[base + 3];
        bb[l]  = (const float*)d_in[base + 4];
    }
    const float* Wbi = (const float*)d_in[23];
    const float* bbi = (const float*)d_in[24];
    const float* Wm1 = (const float*)d_in[25];
    const float* bm1 = (const float*)d_in[26];
    const float* Wm2 = (const float*)d_in[27];
    const float* bm2 = (const float*)d_in[28];
    const float* Wm3 = (const float*)d_in[29];
    const float* bm3 = (const float*)d_in[30];
    float* out = (float*)d_out;

    float *xlr, *cnt, *msum, *m1;
    __nv_bfloat16 *xb, *h1, *h2, *Wlrt, *UVt, *ABb, *bib, *Wm1pt;
    int *deg, *pos;
    cudaGetSymbolAddress((void**)&xb, g_xb);
    cudaGetSymbolAddress((void**)&h1, g_h1);
    cudaGetSymbolAddress((void**)&h2, g_h2);
    cudaGetSymbolAddress((void**)&xlr, g_xlr);
    cudaGetSymbolAddress((void**)&Wlrt, g_Wlrt);
    cudaGetSymbolAddress((void**)&UVt, g_UVt);
    cudaGetSymbolAddress((void**)&ABb, g_ABb);
    cudaGetSymbolAddress((void**)&cnt, g_cnt);
    cudaGetSymbolAddress((void**)&msum, g_msum);
    cudaGetSymbolAddress((void**)&deg, g_deg);
    cudaGetSymbolAddress((void**)&pos, g_pos);
    cudaGetSymbolAddress((void**)&bib, g_bib);
    cudaGetSymbolAddress((void**)&m1, g_m1);
    cudaGetSymbolAddress((void**)&Wm1pt, g_Wm1pt);

    cudaFuncSetAttribute(bf16gemm<float, false>,
                         cudaFuncAttributeMaxDynamicSharedMemorySize, GSMEM);
    cudaFuncSetAttribute(bf16gemm<__nv_bfloat16, false>,
                         cudaFuncAttributeMaxDynamicSharedMemorySize, GSMEM);
    cudaFuncSetAttribute(bf16gemm<float, true>,
                         cudaFuncAttributeMaxDynamicSharedMemorySize, GSMEM);

    // edge_attr mean for self loops
    cudaMemsetAsync(cnt, 0, NN * sizeof(float));
    cudaMemsetAsync(msum, 0, NN * ED * sizeof(float));
    k_count<<<(EE * ED + 255) / 256, 256>>>(dst, edge_attr);
    k_mean<<<(NN * ED + 255) / 256, 256>>>();

    // CSR build (augmented graph, keyed by dst)
    cudaMemsetAsync(deg, 0, NN * sizeof(int));
    cudaMemsetAsync(pos, 0, NN * sizeof(int));
    k_deg<<<(EA + 255) / 256, 256>>>(dst);
    k_scan<<<1, 1024>>>();
    k_fill<<<(EA + 255) / 256, 256>>>(dst);

    // x -> bf16
    k_cvtx<<<(NN * 32 / 2 + 255) / 256, 256>>>(x);

    const __nv_bfloat16* hcur = xb;
    int din = 32;
    __nv_bfloat16* hbufs[2] = { h1, h2 };

    for (int l = 0; l < 4; l++) {
        int dout = (l == 0) ? 256 : 512;
        k_packWt<<<dim3(din / 32, 2 * dout / 32), dim3(32, 8)>>>(Wl[l], Wr[l], din, dout);
        bf16gemm<float, false><<<gemm_grid(NN, 2 * dout), 256, GSMEM>>>(
            hcur, Wlrt, xlr, NN, 2 * dout, din);
        __nv_bfloat16* hn = hbufs[l & 1];
        int dorelu = (l < 3) ? 1 : 0;
        if (dout == 256)
            k_gat<8><<<(NN + 7) / 8, 256>>>(src, edge_attr, We[l], att[l], bb[l], hn, dorelu);
        else
            k_gat<16><<<(NN + 7) / 8, 256>>>(src, edge_attr, We[l], att[l], bb[l], hn, dorelu);
        hcur = hn;
        din = dout;
    }

    // edge scoring
    k_packT<<<dim3(KBI, 2), 256>>>(Wbi);
    bf16gemm<__nv_bfloat16, false><<<gemm_grid(NN, CB2), 256, GSMEM>>>(
        hcur, UVt, ABb, NN, CB2, HMAX);
    k_packM1t<<<(NP * KP + 255) / 256, 256>>>(Wm1, bm1);
    k_bilin<<<(EE + 7) / 8, 256>>>(src, dst, edge_attr, bbi);
    bf16gemm<float, true><<<gemm_grid(EE, NP), 256, GSMEM>>>(bib, Wm1pt, m1, EE, NP, KP);
    k_tail<<<(EE + 7) / 8, 256>>>(Wm2, bm2, Wm3, bm3, out);
}

// round 15
// speedup vs baseline: 1.6668x; 1.0231x over previous
#include <cuda_runtime.h>
#include <cuda_bf16.h>
#include <math.h>
#include <stdint.h>

#define NN 10000
#define EE 50000
#define EA 60000      // E + N self loops
#define ED 16
#define KBI 272
#define CBI 4352      // 272*16
#define CB2 8704      // 2*CBI
#define HMAX 512
#define KP 288        // KBI padded (bias row at 272), %32 == 0
#define NP 384        // KBI padded to N%128

// ---------------- scratch (static device globals; no runtime alloc) ----------------
__device__ __nv_bfloat16 g_xb[NN * 32];             // x converted to bf16
__device__ __nv_bfloat16 g_h1[NN * HMAX];
__device__ __nv_bfloat16 g_h2[NN * HMAX];
__device__ __nv_bfloat16 g_xlrb[NN * 1024];         // [node][xl(dout) | xr(dout)] bf16
__device__ float g_cnt[NN];
__device__ float g_msum[NN * ED];
__device__ float g_mean[NN * ED];
__device__ int   g_off[NN + 1];
__device__ int   g_pos[NN];
__device__ int   g_eid[EA];
__device__ __nv_bfloat16 g_Wlrt[1024 * HMAX];       // TRANSPOSED [c(2*dout)][k] bf16
__device__ __nv_bfloat16 g_UVt[(size_t)CB2 * HMAX]; // TRANSPOSED [c][i] bf16
__device__ __nv_bfloat16 g_ABb[(size_t)NN * CB2];   // per-node factors, bf16
__device__ __nv_bfloat16 g_bib[(size_t)EE * KP];    // bilinear output + bias col, bf16
__device__ __nv_bfloat16 g_m1b[(size_t)EE * NP];    // relu(bi@Wm1+bm1) bf16
__device__ __nv_bfloat16 g_Wm1pt[NP * KP];          // TRANSPOSED padded Wm1 [o][r] bf16

// ---------------- helpers ----------------
__device__ __forceinline__ uint32_t bfpair(float lo, float hi) {
    __nv_bfloat162 h2 = __floats2bfloat162_rn(lo, hi);
    return *reinterpret_cast<uint32_t*>(&h2);
}
__device__ __forceinline__ void ldsm_x4(uint32_t& r0, uint32_t& r1, uint32_t& r2,
                                        uint32_t& r3, uint32_t addr) {
    asm volatile("ldmatrix.sync.aligned.m8n8.x4.shared.b16 {%0,%1,%2,%3}, [%4];"
                 : "=r"(r0), "=r"(r1), "=r"(r2), "=r"(r3) : "r"(addr));
}
__device__ __forceinline__ void cpa16(uint32_t dst, const void* src, int sz) {
    asm volatile("cp.async.cg.shared.global [%0], [%1], 16, %2;"
                 :: "r"(dst), "l"(src), "r"(sz) : "memory");
}

// ---------------- edge_attr mean per dst (self-loop fill 'mean') ----------------
__global__ void k_count(const int* __restrict__ dst, const float* __restrict__ ea) {
    int idx = blockIdx.x * blockDim.x + threadIdx.x;
    if (idx >= EE * ED) return;
    int e = idx >> 4, j = idx & 15;
    int d = dst[e];
    atomicAdd(&g_msum[d * ED + j], ea[idx]);
    if (j == 0) atomicAdd(&g_cnt[d], 1.0f);
}
__global__ void k_mean() {
    int idx = blockIdx.x * blockDim.x + threadIdx.x;
    if (idx >= NN * ED) return;
    g_mean[idx] = g_msum[idx] / fmaxf(g_cnt[idx >> 4], 1.0f);
}

// ---------------- CSR build over augmented edges (dst = sort key) ----------------
// deg[n] == cnt[n] + 1 (self loop), so the scan reads g_cnt directly.
__global__ void k_scan() {
    __shared__ int wsum[32];
    int tid = threadIdx.x, lane = tid & 31, w = tid >> 5;
    int base = 0;
    for (int start = 0; start < NN; start += 1024) {
        int i = start + tid;
        int x = (i < NN) ? ((int)g_cnt[i] + 1) : 0;
#pragma unroll
        for (int o = 1; o < 32; o <<= 1) {
            int t = __shfl_up_sync(0xffffffffu, x, o);
            if (lane >= o) x += t;
        }
        if (lane == 31) wsum[w] = x;
        __syncthreads();
        if (w == 0) {
            int s = wsum[lane];
#pragma unroll
            for (int o = 1; o < 32; o <<= 1) {
                int t = __shfl_up_sync(0xffffffffu, s, o);
                if (lane >= o) s += t;
            }
            wsum[lane] = s;
        }
        __syncthreads();
        int off = (w > 0) ? wsum[w - 1] : 0;
        if (i < NN) g_off[i + 1] = base + off + x;
        base += wsum[31];
        __syncthreads();
    }
    if (tid == 0) g_off[0] = 0;
}
__global__ void k_fill(const int* __restrict__ dst) {
    int e = blockIdx.x * blockDim.x + threadIdx.x;
    if (e >= EA) return;
    int d = (e < EE) ? dst[e] : (e - EE);
    int p = atomicAdd(&g_pos[d], 1);
    g_eid[g_off[d] + p] = e;
}

// ---------------- x -> bf16 ----------------
__global__ void k_cvtx(const float* __restrict__ x) {
    int idx = blockIdx.x * blockDim.x + threadIdx.x;
    if (idx >= NN * 32 / 2) return;
    float2 v = *(const float2*)(x + idx * 2);
    *(uint32_t*)(g_xb + idx * 2) = bfpair(v.x, v.y);
}

// ------- BF16 mma.sync GEMM v2: C[M,N] = A[M,K] * Bt[N,K]^T, bf16 operands --------------
// Both operands K-major. cp.async 3-stage pipeline, ldmatrix fragments.
// BM=BN=128, BK=32, 256 threads = 8 warps (4 in M x 2 in N), warp tile 32x64.
// Requires: N % 128 == 0, K % 32 == 0. M arbitrary (guarded, zero-filled).
#define SROW 20
#define GBUF (128 * SROW * 4)      // 10240 B per operand per stage
#define GSMEM (6 * GBUF)           // 3 stages x 2 operands = 61440 B
template <typename OutT, bool RELU>
__global__ __launch_bounds__(256) void bf16gemm(
        const __nv_bfloat16* __restrict__ A, const __nv_bfloat16* __restrict__ Bt,
        OutT* __restrict__ C, int M, int N, int K) {
    extern __shared__ char dynsm[];
    uint32_t smA;
    {
        uint64_t a64 = (uint64_t)__cvta_generic_to_shared(dynsm);
        smA = (uint32_t)a64;
    }
    const uint32_t smB0 = smA + 3 * GBUF;

    int tid = threadIdx.x;
    int lane = tid & 31, wid = tid >> 5;
    int g = lane >> 2, t = lane & 3;
    int wm = (wid & 3) * 32;
    int wn = (wid >> 2) * 64;
    int brow = blockIdx.y * 128;
    int bcol = blockIdx.x * 128;

    float c[2][8][4];
#pragma unroll
    for (int mi = 0; mi < 2; mi++)
#pragma unroll
        for (int nf = 0; nf < 8; nf++)
#pragma unroll
            for (int q = 0; q < 4; q++) c[mi][nf][q] = 0.0f;

    int arow = tid >> 1;
    int ahalf = tid & 1;
    bool a_ok = (brow + arow) < M;
    const __nv_bfloat16* Aip = A + (size_t)(brow + arow) * K + ahalf * 16;
    const __nv_bfloat16* Bip = Bt + (size_t)(bcol + arow) * K + ahalf * 16;
    uint32_t soff = (uint32_t)(arow * SROW + ahalf * 8) * 4u;
    int asz = a_ok ? 16 : 0;

    int nslab = K >> 5;
    auto issue = [&](int s) {
        int buf = s % 3;
        int k0 = s << 5;
        uint32_t da = smA + buf * GBUF + soff;
        uint32_t db = smB0 + buf * GBUF + soff;
        cpa16(da, Aip + k0, asz);
        cpa16(da + 16, Aip + k0 + 8, asz);
        cpa16(db, Bip + k0, 16);
        cpa16(db + 16, Bip + k0 + 8, 16);
        asm volatile("cp.async.commit_group;" ::: "memory");
    };

    issue(0);
    if (nslab > 1) issue(1);

    for (int s = 0; s < nslab; s++) {
        if (s + 1 < nslab)
            asm volatile("cp.async.wait_group 1;" ::: "memory");
        else
            asm volatile("cp.async.wait_group 0;" ::: "memory");
        __syncthreads();
        int buf = s % 3;
        uint32_t baseA = smA + buf * GBUF;
        uint32_t baseB = smB0 + buf * GBUF;
#pragma unroll
        for (int ks = 0; ks < 2; ks++) {
            uint32_t a[2][4], b[8][2];
#pragma unroll
            for (int mi = 0; mi < 2; mi++) {
                int row = wm + mi * 16 + (lane & 7) + ((lane >> 3) & 1) * 8;
                int seg = ks * 2 + (lane >> 4);
                ldsm_x4(a[mi][0], a[mi][1], a[mi][2], a[mi][3],
                        baseA + (uint32_t)(row * SROW + seg * 4) * 4u);
            }
#pragma unroll
            for (int p = 0; p < 4; p++) {
                int nf = p * 2;
                int col = wn + (nf + (lane >> 4)) * 8 + (lane & 7);
                int seg = ks * 2 + ((lane >> 3) & 1);
                ldsm_x4(b[nf][0], b[nf][1], b[nf + 1][0], b[nf + 1][1],
                        baseB + (uint32_t)(col * SROW + seg * 4) * 4u);
            }
#pragma unroll
            for (int mi = 0; mi < 2; mi++)
#pragma unroll
                for (int nf = 0; nf < 8; nf++) {
                    asm volatile(
                        "mma.sync.aligned.m16n8k16.row.col.f32.bf16.bf16.f32 "
                        "{%0,%1,%2,%3}, {%4,%5,%6,%7}, {%8,%9}, {%0,%1,%2,%3};"
                        : "+f"(c[mi][nf][0]), "+f"(c[mi][nf][1]),
                          "+f"(c[mi][nf][2]), "+f"(c[mi][nf][3])
                        : "r"(a[mi][0]), "r"(a[mi][1]), "r"(a[mi][2]), "r"(a[mi][3]),
                          "r"(b[nf][0]), "r"(b[nf][1]));
                }
        }
        if (s + 2 < nslab) issue(s + 2);
    }

#pragma unroll
    for (int mi = 0; mi < 2; mi++) {
        int row0 = brow + wm + mi * 16 + g;
#pragma unroll
        for (int nf = 0; nf < 8; nf++) {
            int col = bcol + wn + nf * 8 + 2 * t;
            float v0 = c[mi][nf][0], v1 = c[mi][nf][1];
            float v2 = c[mi][nf][2], v3 = c[mi][nf][3];
            if (RELU) {
                v0 = fmaxf(v0, 0.f); v1 = fmaxf(v1, 0.f);
                v2 = fmaxf(v2, 0.f); v3 = fmaxf(v3, 0.f);
            }
            if (sizeof(OutT) == 4) {
                float* Cf = (float*)C;
                if (row0 < M)
                    *(float2*)(Cf + (size_t)row0 * N + col) = make_float2(v0, v1);
                if (row0 + 8 < M)
                    *(float2*)(Cf + (size_t)(row0 + 8) * N + col) = make_float2(v2, v3);
            } else {
                __nv_bfloat16* Cb = (__nv_bfloat16*)C;
                if (row0 < M)
                    *(uint32_t*)(Cb + (size_t)row0 * N + col) = bfpair(v0, v1);
                if (row0 + 8 < M)
                    *(uint32_t*)(Cb + (size_t)(row0 + 8) * N + col) = bfpair(v2, v3);
            }
        }
    }
}

// ------- pack Wl|Wr TRANSPOSED -> g_Wlrt[c][k], c in [0,2*dout), 32x32 smem tiles --------
__global__ void k_packWt(const float* __restrict__ Wl, const float* __restrict__ Wr,
                         int K, int dout) {
    __shared__ float tile[32][33];
    int kb = blockIdx.x * 32, cb = blockIdx.y * 32;
    int tx = threadIdx.x, ty = threadIdx.y;   // 32x8
    const float* W = (cb < dout) ? Wl : Wr;
    int csrc = (cb < dout) ? cb : cb - dout;
    for (int i = ty; i < 32; i += 8)
        tile[i][tx] = W[(size_t)(kb + i) * dout + csrc + tx];
    __syncthreads();
    for (int i = ty; i < 32; i += 8)
        g_Wlrt[(size_t)(cb + i) * K + kb + tx] = __float2bfloat16(tile[tx][i]);
}

// ---------------- fused GAT layer: alpha + online softmax + aggregation (warp/node) ------
// xlr is bf16; each lane owns 2 adjacent channels (bfloat162 loads, fully coalesced).
template <int NC2>   // NC2 = dout/64
__global__ __launch_bounds__(256) void k_gat(
        const int* __restrict__ src, const float* __restrict__ ea,
        const float* __restrict__ We, const float* __restrict__ att,
        const float* __restrict__ bias, __nv_bfloat16* __restrict__ hn, int dorelu) {
    const int dout = NC2 * 64;
    __shared__ float2 sWe[ED][NC2 * 32];
    __shared__ float2 sAtt[NC2 * 32];
    __shared__ float2 sB[NC2 * 32];
    int tid = threadIdx.x;
    for (int i = tid; i < ED * dout / 2; i += 256)
        sWe[i / (dout / 2)][i % (dout / 2)] = ((const float2*)We)[i];
    for (int i = tid; i < dout / 2; i += 256) {
        sAtt[i] = ((const float2*)att)[i];
        sB[i] = ((const float2*)bias)[i];
    }
    __syncthreads();

    int lane = tid & 31, w = tid >> 5;
    int n = blockIdx.x * 8 + w;
    if (n >= NN) return;

    const __nv_bfloat16* xrp = g_xlrb + (size_t)n * 2 * dout + dout;
    float2 xrv[NC2];
#pragma unroll
    for (int q = 0; q < NC2; q++)
        xrv[q] = __bfloat1622float2(*(const __nv_bfloat162*)(xrp + q * 64 + lane * 2));

    float m = -1e30f, ssum = 0.0f;
    float2 acc[NC2];
#pragma unroll
    for (int q = 0; q < NC2; q++) acc[q] = make_float2(0.0f, 0.0f);

    int beg = g_off[n], end = g_off[n + 1];
    for (int i = beg; i < end; i++) {
        int e = g_eid[i];
        int s;
        const float* eap;
        if (e < EE) { s = src[e]; eap = ea + (size_t)e * ED; }
        else        { s = e - EE; eap = g_mean + (size_t)s * ED; }
        float eareg = (lane < ED) ? eap[lane] : 0.0f;
        const __nv_bfloat16* xlp = g_xlrb + (size_t)s * 2 * dout;
        float2 xv[NC2];
#pragma unroll
        for (int q = 0; q < NC2; q++)
            xv[q] = __bfloat1622float2(*(const __nv_bfloat162*)(xlp + q * 64 + lane * 2));
        float2 ed[NC2];
#pragma unroll
        for (int q = 0; q < NC2; q++) ed[q] = make_float2(0.0f, 0.0f);
#pragma unroll
        for (int j = 0; j < ED; j++) {
            float aj = __shfl_sync(0xffffffffu, eareg, j);
#pragma unroll
            for (int q = 0; q < NC2; q++) {
                float2 wv = sWe[j][q * 32 + lane];
                ed[q].x += aj * wv.x;
                ed[q].y += aj * wv.y;
            }
        }
        float p = 0.0f;
#pragma unroll
        for (int q = 0; q < NC2; q++) {
            float2 av = sAtt[q * 32 + lane];
            float v0 = xv[q].x + xrv[q].x + ed[q].x;
            float v1 = xv[q].y + xrv[q].y + ed[q].y;
            v0 = v0 > 0.0f ? v0 : 0.2f * v0;
            v1 = v1 > 0.0f ? v1 : 0.2f * v1;
            p += av.x * v0 + av.y * v1;
        }
#pragma unroll
        for (int o = 16; o; o >>= 1) p += __shfl_xor_sync(0xffffffffu, p, o);
        float nm = fmaxf(m, p);
        float cs = expf(m - nm);
        float ex = expf(p - nm);
        ssum = ssum * cs + ex;
#pragma unroll
        for (int q = 0; q < NC2; q++) {
            acc[q].x = acc[q].x * cs + ex * xv[q].x;
            acc[q].y = acc[q].y * cs + ex * xv[q].y;
        }
        m = nm;
    }
    float inv = 1.0f / fmaxf(ssum, 1e-16f);
    __nv_bfloat16* hp = hn + (size_t)n * dout;
#pragma unroll
    for (int q = 0; q < NC2; q++) {
        float2 bv = sB[q * 32 + lane];
        float v0 = acc[q].x * inv + bv.x;
        float v1 = acc[q].y * inv + bv.y;
        if (dorelu) { v0 = fmaxf(v0, 0.0f); v1 = fmaxf(v1, 0.0f); }
        *(uint32_t*)(hp + q * 64 + lane * 2) = bfpair(v0, v1);
    }
}

// ---- pack Wbi[k,i,j] -> TRANSPOSED g_UVt[isV*CBI + k*16 + j][i], bf16, smem transpose ----
__global__ void k_packT(const float* __restrict__ Wbi) {
    __shared__ __nv_bfloat16 sb[512 * 17];
    int k = blockIdx.x, isV = blockIdx.y, tid = threadIdx.x;
    const float* src = Wbi + ((size_t)k * 1024 + isV * 512) * 16;
#pragma unroll
    for (int q = 0; q < 8; q++) {
        int idx = tid + q * 256;               // 0..2047 float4s over [i(512)][j(16)]
        float4 v = ((const float4*)src)[idx];
        int i = idx >> 2, j4 = (idx & 3) * 4;
        sb[i * 17 + j4 + 0] = __float2bfloat16(v.x);
        sb[i * 17 + j4 + 1] = __float2bfloat16(v.y);
        sb[i * 17 + j4 + 2] = __float2bfloat16(v.z);
        sb[i * 17 + j4 + 3] = __float2bfloat16(v.w);
    }
    __syncthreads();
#pragma unroll
    for (int q = 0; q < 16; q++) {
        int idx = tid + q * 256;               // 0..4095 uint32s: [j(16)][ipair(256)]
        int j = idx >> 8, ip = idx & 255, i0 = ip * 2;
        __nv_bfloat162 h2 = __halves2bfloat162(sb[i0 * 17 + j], sb[(i0 + 1) * 17 + j]);
        *(uint32_t*)(g_UVt + ((size_t)(isV * CBI + k * 16 + j)) * HMAX + i0) =
            *reinterpret_cast<uint32_t*>(&h2);
    }
}

// ---------------- pad Wm1 TRANSPOSED into [NP][KP] bf16 with bias row ----------------
__global__ void k_packM1t(const float* __restrict__ Wm1, const float* __restrict__ bm1) {
    int idx = blockIdx.x * blockDim.x + threadIdx.x;
    if (idx >= NP * KP) return;
    int o = idx / KP, r = idx % KP;
    float v = 0.0f;
    if (o < KBI) {
        if (r < KBI) v = Wm1[(size_t)r * KBI + o];
        else if (r == KBI) v = bm1[o];
    }
    g_Wm1pt[idx] = __float2bfloat16(v);
}

// ---- bilinear in CSR order (dst-sorted for L2 locality on B[dst]) ----
// bi[e][k] = sum_j (A[src]+B[dst])[k*16+j]*ea[j] + bbi[k]; only real edges (e < EE).
__global__ void k_bilin(const int* __restrict__ src, const int* __restrict__ dst,
                        const float* __restrict__ ea, const float* __restrict__ bbi) {
    int tid = threadIdx.x, w = tid >> 5, lane = tid & 31;
    int i = blockIdx.x * 8 + w;
    if (i >= EA) return;
    int e = g_eid[i];
    if (e >= EE) return;     // self loops are not scored
    int s = src[e], d = dst[e];
    int j4 = lane & 3, kk = lane >> 2;
    float4 eav = *(const float4*)(ea + (size_t)e * ED + j4 * 4);
    const __nv_bfloat16* Ap = g_ABb + (size_t)s * CB2;
    const __nv_bfloat16* Bp = g_ABb + (size_t)d * CB2 + CBI;
    __nv_bfloat16* bo = g_bib + (size_t)e * KP;
#pragma unroll 4
    for (int it = 0; it < 34; it++) {
        int base = (it * 8 + kk) * 16 + j4 * 4;
        float2 a01 = __bfloat1622float2(*(const __nv_bfloat162*)(Ap + base));
        float2 a23 = __bfloat1622float2(*(const __nv_bfloat162*)(Ap + base + 2));
        float2 b01 = __bfloat1622float2(*(const __nv_bfloat162*)(Bp + base));
        float2 b23 = __bfloat1622float2(*(const __nv_bfloat162*)(Bp + base + 2));
        float v = (a01.x + b01.x) * eav.x + (a01.y + b01.y) * eav.y
                + (a23.x + b23.x) * eav.z + (a23.y + b23.y) * eav.w;
        v += __shfl_xor_sync(0xffffffffu, v, 1);
        v += __shfl_xor_sync(0xffffffffu, v, 2);
        if (j4 == 0) {
            int k = it * 8 + kk;
            bo[k] = __float2bfloat16(v + bbi[k]);
        }
    }
    if (lane < KP - KBI)
        bo[KBI + lane] = __float2bfloat16(lane == 0 ? 1.0f : 0.0f);
}

// ---------------- tail: m2 = relu(m1@Wm2+bm2); out = sigmoid(m2@Wm3+bm3) ------------------
__global__ void k_tail(const float* __restrict__ Wm2, const float* __restrict__ bm2,
                       const float* __restrict__ Wm3, const float* __restrict__ bm3,
                       float* __restrict__ out) {
    int tid = threadIdx.x, w = tid >> 5, lane = tid & 31;
    int e = blockIdx.x * 8 + w;
    if (e >= EE) return;
    const __nv_bfloat16* m1p = g_m1b + (size_t)e * NP;
    float acc = bm2[lane];
    for (int k0 = 0; k0 < KBI; k0 += 32) {
        float mv = __bfloat162float(m1p[k0 + lane]);
        int jmax = (KBI - k0 < 32) ? (KBI - k0) : 32;
        for (int j = 0; j < jmax; j++) {
            float m = __shfl_sync(0xffffffffu, mv, j);
            acc += m * Wm2[(size_t)(k0 + j) * 32 + lane];
        }
    }
    float m2v = fmaxf(acc, 0.0f);
    float p = m2v * Wm3[lane];
#pragma unroll
    for (int o = 16; o; o >>= 1) p += __shfl_xor_sync(0xffffffffu, p, o);
    if (lane == 0) out[e] = 1.0f / (1.0f + expf(-(p + bm3[0])));
}

// ---------------- host ----------------
static inline dim3 gemm_grid(int M, int Nn) { return dim3(Nn / 128, (M + 127) / 128); }

extern "C" void kernel_launch(void* const* d_in, const int* in_sizes, int n_in,
                              void* d_out, int out_size) {
    const float* x         = (const float*)d_in[0];
    const float* edge_attr = (const float*)d_in[1];
    const int*   eidx      = (const int*)d_in[2];
    const int* src = eidx;
    const int* dst = eidx + EE;
    const float *Wl[4], *Wr[4], *We[4], *att[4], *bb[4];
    for (int l = 0; l < 4; l++) {
        int base = 3 + l * 5;
        Wl[l]  = (const float*)d_in[base + 0];
        Wr[l]  = (const float*)d_in[base + 1];
        We[l]  = (const float*)d_in[base + 2];
        att[l] = (const float*)d_in[base + 3];
        bb[l]  = (const float*)d_in[base + 4];
    }
    const float* Wbi = (const float*)d_in[23];
    const float* bbi = (const float*)d_in[24];
    const float* Wm1 = (const float*)d_in[25];
    const float* bm1 = (const float*)d_in[26];
    const float* Wm2 = (const float*)d_in[27];
    const float* bm2 = (const float*)d_in[28];
    const float* Wm3 = (const float*)d_in[29];
    const float* bm3 = (const float*)d_in[30];
    float* out = (float*)d_out;

    float *cnt, *msum;
    __nv_bfloat16 *xb, *h1, *h2, *xlrb, *Wlrt, *UVt, *ABb, *bib, *m1b, *Wm1pt;
    int *pos;
    cudaGetSymbolAddress((void**)&xb, g_xb);
    cudaGetSymbolAddress((void**)&h1, g_h1);
    cudaGetSymbolAddress((void**)&h2, g_h2);
    cudaGetSymbolAddress((void**)&xlrb, g_xlrb);
    cudaGetSymbolAddress((void**)&Wlrt, g_Wlrt);
    cudaGetSymbolAddress((void**)&UVt, g_UVt);
    cudaGetSymbolAddress((void**)&ABb, g_ABb);
    cudaGetSymbolAddress((void**)&cnt, g_cnt);
    cudaGetSymbolAddress((void**)&msum, g_msum);
    cudaGetSymbolAddress((void**)&pos, g_pos);
    cudaGetSymbolAddress((void**)&bib, g_bib);
    cudaGetSymbolAddress((void**)&m1b, g_m1b);
    cudaGetSymbolAddress((void**)&Wm1pt, g_Wm1pt);

    cudaFuncSetAttribute(bf16gemm<__nv_bfloat16, false>,
                         cudaFuncAttributeMaxDynamicSharedMemorySize, GSMEM);
    cudaFuncSetAttribute(bf16gemm<__nv_bfloat16, true>,
                         cudaFuncAttributeMaxDynamicSharedMemorySize, GSMEM);

    // edge_attr mean for self loops
    cudaMemsetAsync(cnt, 0, NN * sizeof(float));
    cudaMemsetAsync(msum, 0, NN * ED * sizeof(float));
    k_count<<<(EE * ED + 255) / 256, 256>>>(dst, edge_attr);
    k_mean<<<(NN * ED + 255) / 256, 256>>>();

    // CSR build (augmented graph, keyed by dst); deg derived from cnt
    cudaMemsetAsync(pos, 0, NN * sizeof(int));
    k_scan<<<1, 1024>>>();
    k_fill<<<(EA + 255) / 256, 256>>>(dst);

    // x -> bf16
    k_cvtx<<<(NN * 32 / 2 + 255) / 256, 256>>>(x);

    const __nv_bfloat16* hcur = xb;
    int din = 32;
    __nv_bfloat16* hbufs[2] = { h1, h2 };

    for (int l = 0; l < 4; l++) {
        int dout = (l == 0) ? 256 : 512;
        k_packWt<<<dim3(din / 32, 2 * dout / 32), dim3(32, 8)>>>(Wl[l], Wr[l], din, dout);
        bf16gemm<__nv_bfloat16, false><<<gemm_grid(NN, 2 * dout), 256, GSMEM>>>(
            hcur, Wlrt, xlrb, NN, 2 * dout, din);
        __nv_bfloat16* hn = hbufs[l & 1];
        int dorelu = (l < 3) ? 1 : 0;
        if (dout == 256)
            k_gat<4><<<(NN + 7) / 8, 256>>>(src, edge_attr, We[l], att[l], bb[l], hn, dorelu);
        else
            k_gat<8><<<(NN + 7) / 8, 256>>>(src, edge_attr, We[l], att[l], bb[l], hn, dorelu);
        hcur = hn;
        din = dout;
    }

    // edge scoring
    k_packT<<<dim3(KBI, 2), 256>>>(Wbi);
    bf16gemm<__nv_bfloat16, false><<<gemm_grid(NN, CB2), 256, GSMEM>>>(
        hcur, UVt, ABb, NN, CB2, HMAX);
    k_packM1t<<<(NP * KP + 255) / 256, 256>>>(Wm1, bm1);
    k_bilin<<<(EA + 7) / 8, 256>>>(src, dst, edge_attr, bbi);
    bf16gemm<__nv_bfloat16, true><<<gemm_grid(EE, NP), 256, GSMEM>>>(
        bib, Wm1pt, m1b, EE, NP, KP);
    k_tail<<<(EE + 7) / 8, 256>>>(Wm2, bm2, Wm3, bm3, out);
}

// round 16
// speedup vs baseline: 1.6689x; 1.0013x over previous
#include <cuda_runtime.h>
#include <cuda_bf16.h>
#include <math.h>
#include <stdint.h>

#define NN 10000
#define EE 50000
#define EA 60000      // E + N self loops
#define ED 16
#define KBI 272
#define CBI 4352      // 272*16
#define CB2 8704      // 2*CBI
#define HMAX 512
#define KP 288        // KBI padded (bias row at 272), %32 == 0
#define NP 384        // KBI padded to N%128

// ---------------- scratch (static device globals; no runtime alloc) ----------------
__device__ __nv_bfloat16 g_xb[NN * 32];             // x converted to bf16
__device__ __nv_bfloat16 g_h1[NN * HMAX];
__device__ __nv_bfloat16 g_h2[NN * HMAX];
__device__ __nv_bfloat16 g_xlrb[NN * 1024];         // [node][xl(dout) | xr(dout)] bf16
__device__ float g_cnt[NN];
__device__ float g_msum[NN * ED];
__device__ float g_mean[NN * ED];
__device__ int   g_off[NN + 1];
__device__ int   g_pos[NN];
__device__ int   g_eid[EA];
__device__ __nv_bfloat16 g_Wlrt[1024 * HMAX];       // TRANSPOSED [c(2*dout)][k] bf16
__device__ __nv_bfloat16 g_UVt[(size_t)CB2 * HMAX]; // TRANSPOSED [c][i] bf16
__device__ __nv_bfloat16 g_ABb[(size_t)NN * CB2];   // per-node factors, bf16
__device__ __nv_bfloat16 g_bib[(size_t)EE * KP];    // bilinear output + bias col, bf16
__device__ __nv_bfloat16 g_Wm1pt[NP * KP];          // TRANSPOSED padded Wm1 [o][r] bf16

// ---------------- helpers ----------------
__device__ __forceinline__ uint32_t bfpair(float lo, float hi) {
    __nv_bfloat162 h2 = __floats2bfloat162_rn(lo, hi);
    return *reinterpret_cast<uint32_t*>(&h2);
}
__device__ __forceinline__ void ldsm_x4(uint32_t& r0, uint32_t& r1, uint32_t& r2,
                                        uint32_t& r3, uint32_t addr) {
    asm volatile("ldmatrix.sync.aligned.m8n8.x4.shared.b16 {%0,%1,%2,%3}, [%4];"
                 : "=r"(r0), "=r"(r1), "=r"(r2), "=r"(r3) : "r"(addr));
}
__device__ __forceinline__ void cpa16(uint32_t dst, const void* src, int sz) {
    asm volatile("cp.async.cg.shared.global [%0], [%1], 16, %2;"
                 :: "r"(dst), "l"(src), "r"(sz) : "memory");
}

// ---------------- edge_attr mean per dst (self-loop fill 'mean') ----------------
__global__ void k_count(const int* __restrict__ dst, const float* __restrict__ ea) {
    int idx = blockIdx.x * blockDim.x + threadIdx.x;
    if (idx >= EE * ED) return;
    int e = idx >> 4, j = idx & 15;
    int d = dst[e];
    atomicAdd(&g_msum[d * ED + j], ea[idx]);
    if (j == 0) atomicAdd(&g_cnt[d], 1.0f);
}
__global__ void k_mean() {
    int idx = blockIdx.x * blockDim.x + threadIdx.x;
    if (idx >= NN * ED) return;
    g_mean[idx] = g_msum[idx] / fmaxf(g_cnt[idx >> 4], 1.0f);
}

// ---------------- CSR build over augmented edges (dst = sort key) ----------------
__global__ void k_scan() {
    __shared__ int wsum[32];
    int tid = threadIdx.x, lane = tid & 31, w = tid >> 5;
    int base = 0;
    for (int start = 0; start < NN; start += 1024) {
        int i = start + tid;
        int x = (i < NN) ? ((int)g_cnt[i] + 1) : 0;
#pragma unroll
        for (int o = 1; o < 32; o <<= 1) {
            int t = __shfl_up_sync(0xffffffffu, x, o);
            if (lane >= o) x += t;
        }
        if (lane == 31) wsum[w] = x;
        __syncthreads();
        if (w == 0) {
            int s = wsum[lane];
#pragma unroll
            for (int o = 1; o < 32; o <<= 1) {
                int t = __shfl_up_sync(0xffffffffu, s, o);
                if (lane >= o) s += t;
            }
            wsum[lane] = s;
        }
        __syncthreads();
        int off = (w > 0) ? wsum[w - 1] : 0;
        if (i < NN) g_off[i + 1] = base + off + x;
        base += wsum[31];
        __syncthreads();
    }
    if (tid == 0) g_off[0] = 0;
}
__global__ void k_fill(const int* __restrict__ dst) {
    int e = blockIdx.x * blockDim.x + threadIdx.x;
    if (e >= EA) return;
    int d = (e < EE) ? dst[e] : (e - EE);
    int p = atomicAdd(&g_pos[d], 1);
    g_eid[g_off[d] + p] = e;
}

// ---------------- x -> bf16 ----------------
__global__ void k_cvtx(const float* __restrict__ x) {
    int idx = blockIdx.x * blockDim.x + threadIdx.x;
    if (idx >= NN * 32 / 2) return;
    float2 v = *(const float2*)(x + idx * 2);
    *(uint32_t*)(g_xb + idx * 2) = bfpair(v.x, v.y);
}

// ------- BF16 mma.sync GEMM v2: C[M,N] = A[M,K] * Bt[N,K]^T, bf16 operands --------------
#define SROW 20
#define GBUF (128 * SROW * 4)      // 10240 B per operand per stage
#define GSMEM (6 * GBUF)           // 3 stages x 2 operands = 61440 B
template <typename OutT, bool RELU>
__global__ __launch_bounds__(256) void bf16gemm(
        const __nv_bfloat16* __restrict__ A, const __nv_bfloat16* __restrict__ Bt,
        OutT* __restrict__ C, int M, int N, int K) {
    extern __shared__ char dynsm[];
    uint32_t smA;
    {
        uint64_t a64 = (uint64_t)__cvta_generic_to_shared(dynsm);
        smA = (uint32_t)a64;
    }
    const uint32_t smB0 = smA + 3 * GBUF;

    int tid = threadIdx.x;
    int lane = tid & 31, wid = tid >> 5;
    int g = lane >> 2, t = lane & 3;
    int wm = (wid & 3) * 32;
    int wn = (wid >> 2) * 64;
    int brow = blockIdx.y * 128;
    int bcol = blockIdx.x * 128;

    float c[2][8][4];
#pragma unroll
    for (int mi = 0; mi < 2; mi++)
#pragma unroll
        for (int nf = 0; nf < 8; nf++)
#pragma unroll
            for (int q = 0; q < 4; q++) c[mi][nf][q] = 0.0f;

    int arow = tid >> 1;
    int ahalf = tid & 1;
    bool a_ok = (brow + arow) < M;
    const __nv_bfloat16* Aip = A + (size_t)(brow + arow) * K + ahalf * 16;
    const __nv_bfloat16* Bip = Bt + (size_t)(bcol + arow) * K + ahalf * 16;
    uint32_t soff = (uint32_t)(arow * SROW + ahalf * 8) * 4u;
    int asz = a_ok ? 16 : 0;

    int nslab = K >> 5;
    auto issue = [&](int s) {
        int buf = s % 3;
        int k0 = s << 5;
        uint32_t da = smA + buf * GBUF + soff;
        uint32_t db = smB0 + buf * GBUF + soff;
        cpa16(da, Aip + k0, asz);
        cpa16(da + 16, Aip + k0 + 8, asz);
        cpa16(db, Bip + k0, 16);
        cpa16(db + 16, Bip + k0 + 8, 16);
        asm volatile("cp.async.commit_group;" ::: "memory");
    };

    issue(0);
    if (nslab > 1) issue(1);

    for (int s = 0; s < nslab; s++) {
        if (s + 1 < nslab)
            asm volatile("cp.async.wait_group 1;" ::: "memory");
        else
            asm volatile("cp.async.wait_group 0;" ::: "memory");
        __syncthreads();
        int buf = s % 3;
        uint32_t baseA = smA + buf * GBUF;
        uint32_t baseB = smB0 + buf * GBUF;
#pragma unroll
        for (int ks = 0; ks < 2; ks++) {
            uint32_t a[2][4], b[8][2];
#pragma unroll
            for (int mi = 0; mi < 2; mi++) {
                int row = wm + mi * 16 + (lane & 7) + ((lane >> 3) & 1) * 8;
                int seg = ks * 2 + (lane >> 4);
                ldsm_x4(a[mi][0], a[mi][1], a[mi][2], a[mi][3],
                        baseA + (uint32_t)(row * SROW + seg * 4) * 4u);
            }
#pragma unroll
            for (int p = 0; p < 4; p++) {
                int nf = p * 2;
                int col = wn + (nf + (lane >> 4)) * 8 + (lane & 7);
                int seg = ks * 2 + ((lane >> 3) & 1);
                ldsm_x4(b[nf][0], b[nf][1], b[nf + 1][0], b[nf + 1][1],
                        baseB + (uint32_t)(col * SROW + seg * 4) * 4u);
            }
#pragma unroll
            for (int mi = 0; mi < 2; mi++)
#pragma unroll
                for (int nf = 0; nf < 8; nf++) {
                    asm volatile(
                        "mma.sync.aligned.m16n8k16.row.col.f32.bf16.bf16.f32 "
                        "{%0,%1,%2,%3}, {%4,%5,%6,%7}, {%8,%9}, {%0,%1,%2,%3};"
                        : "+f"(c[mi][nf][0]), "+f"(c[mi][nf][1]),
                          "+f"(c[mi][nf][2]), "+f"(c[mi][nf][3])
                        : "r"(a[mi][0]), "r"(a[mi][1]), "r"(a[mi][2]), "r"(a[mi][3]),
                          "r"(b[nf][0]), "r"(b[nf][1]));
                }
        }
        if (s + 2 < nslab) issue(s + 2);
    }

#pragma unroll
    for (int mi = 0; mi < 2; mi++) {
        int row0 = brow + wm + mi * 16 + g;
#pragma unroll
        for (int nf = 0; nf < 8; nf++) {
            int col = bcol + wn + nf * 8 + 2 * t;
            float v0 = c[mi][nf][0], v1 = c[mi][nf][1];
            float v2 = c[mi][nf][2], v3 = c[mi][nf][3];
            if (RELU) {
                v0 = fmaxf(v0, 0.f); v1 = fmaxf(v1, 0.f);
                v2 = fmaxf(v2, 0.f); v3 = fmaxf(v3, 0.f);
            }
            if (sizeof(OutT) == 4) {
                float* Cf = (float*)C;
                if (row0 < M)
                    *(float2*)(Cf + (size_t)row0 * N + col) = make_float2(v0, v1);
                if (row0 + 8 < M)
                    *(float2*)(Cf + (size_t)(row0 + 8) * N + col) = make_float2(v2, v3);
            } else {
                __nv_bfloat16* Cb = (__nv_bfloat16*)C;
                if (row0 < M)
                    *(uint32_t*)(Cb + (size_t)row0 * N + col) = bfpair(v0, v1);
                if (row0 + 8 < M)
                    *(uint32_t*)(Cb + (size_t)(row0 + 8) * N + col) = bfpair(v2, v3);
            }
        }
    }
}

// ======== fused edge MLP: m1 = relu(bib@Wm1pt^T) -> m2 -> sigmoid out ====================
// One CTA per 128 edges. bib tile staged ONCE (9 K-slabs); 3 N-chunks of 128 cols each,
// m2 accumulated in smem fp32; Wm2 staged once; tail fused.
#define ESM_A 0
#define ESM_B (9 * GBUF)                       // 92160
#define ESM_M1 (ESM_B + 2 * GBUF)              // 112640
#define ESM_M2 (ESM_M1 + 128 * 132 * 2)        // 146432
#define ESM_W2 (ESM_M2 + 128 * 32 * 4)         // 162816
#define ESM_TOT (ESM_W2 + KBI * 32 * 4)        // 197632
__global__ __launch_bounds__(256) void k_mlp(
        const float* __restrict__ Wm2, const float* __restrict__ bm2,
        const float* __restrict__ Wm3, const float* __restrict__ bm3,
        float* __restrict__ out) {
    extern __shared__ char sm[];
    uint32_t smb;
    {
        uint64_t a64 = (uint64_t)__cvta_generic_to_shared(sm);
        smb = (uint32_t)a64;
    }
    __nv_bfloat16* s_m1 = (__nv_bfloat16*)(sm + ESM_M1);
    float* s_m2 = (float*)(sm + ESM_M2);
    float* s_w2 = (float*)(sm + ESM_W2);

    int tid = threadIdx.x, lane = tid & 31, wid = tid >> 5;
    int g = lane >> 2, t = lane & 3;
    int wm = (wid & 3) * 32, wn = (wid >> 2) * 64;
    int e0 = blockIdx.x * 128;

    for (int i = tid; i < KBI * 32; i += 256) s_w2[i] = Wm2[i];
    for (int i = tid; i < 128 * 32; i += 256) s_m2[i] = bm2[i & 31];

    int arow = tid >> 1, ahalf = tid & 1;
    bool a_ok = (e0 + arow) < EE;
    const __nv_bfloat16* Aip = g_bib + (size_t)(e0 + arow) * KP + ahalf * 16;
    uint32_t soff = (uint32_t)(arow * SROW + ahalf * 8) * 4u;
    int asz = a_ok ? 16 : 0;
#pragma unroll
    for (int s = 0; s < 9; s++) {
        uint32_t da = smb + ESM_A + s * GBUF + soff;
        cpa16(da, Aip + s * 32, asz);
        cpa16(da + 16, Aip + s * 32 + 8, asz);
    }
    asm volatile("cp.async.commit_group;" ::: "memory");

    for (int nc = 0; nc < 3; nc++) {
        int bcol = nc * 128;
        const __nv_bfloat16* Bip = g_Wm1pt + (size_t)(bcol + arow) * KP + ahalf * 16;
        auto issueB = [&](int s) {
            uint32_t db = smb + ESM_B + (s & 1) * GBUF + soff;
            cpa16(db, Bip + s * 32, 16);
            cpa16(db + 16, Bip + s * 32 + 8, 16);
            asm volatile("cp.async.commit_group;" ::: "memory");
        };
        issueB(0);
        issueB(1);

        float c[2][8][4];
#pragma unroll
        for (int mi = 0; mi < 2; mi++)
#pragma unroll
            for (int nf = 0; nf < 8; nf++)
#pragma unroll
                for (int q = 0; q < 4; q++) c[mi][nf][q] = 0.0f;

        for (int s = 0; s < 9; s++) {
            if (s < 8)
                asm volatile("cp.async.wait_group 1;" ::: "memory");
            else
                asm volatile("cp.async.wait_group 0;" ::: "memory");
            __syncthreads();
            uint32_t baseA = smb + ESM_A + s * GBUF;
            uint32_t baseB = smb + ESM_B + (s & 1) * GBUF;
#pragma unroll
            for (int ks = 0; ks < 2; ks++) {
                uint32_t a[2][4], b[8][2];
#pragma unroll
                for (int mi = 0; mi < 2; mi++) {
                    int row = wm + mi * 16 + (lane & 7) + ((lane >> 3) & 1) * 8;
                    int seg = ks * 2 + (lane >> 4);
                    ldsm_x4(a[mi][0], a[mi][1], a[mi][2], a[mi][3],
                            baseA + (uint32_t)(row * SROW + seg * 4) * 4u);
                }
#pragma unroll
                for (int p = 0; p < 4; p++) {
                    int nf = p * 2;
                    int col = wn + (nf + (lane >> 4)) * 8 + (lane & 7);
                    int seg = ks * 2 + ((lane >> 3) & 1);
                    ldsm_x4(b[nf][0], b[nf][1], b[nf + 1][0], b[nf + 1][1],
                            baseB + (uint32_t)(col * SROW + seg * 4) * 4u);
                }
#pragma unroll
                for (int mi = 0; mi < 2; mi++)
#pragma unroll
                    for (int nf = 0; nf < 8; nf++) {
                        asm volatile(
                            "mma.sync.aligned.m16n8k16.row.col.f32.bf16.bf16.f32 "
                            "{%0,%1,%2,%3}, {%4,%5,%6,%7}, {%8,%9}, {%0,%1,%2,%3};"
                            : "+f"(c[mi][nf][0]), "+f"(c[mi][nf][1]),
                              "+f"(c[mi][nf][2]), "+f"(c[mi][nf][3])
                            : "r"(a[mi][0]), "r"(a[mi][1]), "r"(a[mi][2]), "r"(a[mi][3]),
                              "r"(b[nf][0]), "r"(b[nf][1]));
                    }
            }
            if (s + 2 < 9) issueB(s + 2);
        }
        __syncthreads();
        // epilogue: relu -> bf16 -> s_m1[row][col], row stride 132
#pragma unroll
        for (int mi = 0; mi < 2; mi++) {
            int row0 = wm + mi * 16 + g;
#pragma unroll
            for (int nf = 0; nf < 8; nf++) {
                int col = wn + nf * 8 + 2 * t;
                *(uint32_t*)(s_m1 + row0 * 132 + col) =
                    bfpair(fmaxf(c[mi][nf][0], 0.f), fmaxf(c[mi][nf][1], 0.f));
                *(uint32_t*)(s_m1 + (row0 + 8) * 132 + col) =
                    bfpair(fmaxf(c[mi][nf][2], 0.f), fmaxf(c[mi][nf][3], 0.f));
            }
        }
        __syncthreads();
        // m2 update: warp wid owns rows wid*16..+15; lane owns output o=lane
        int cmax = KBI - bcol;
        if (cmax > 128) cmax = 128;
        for (int rr = 0; rr < 16; rr++) {
            int row = wid * 16 + rr;
            float acc = s_m2[row * 32 + lane];
            for (int cb = 0; cb * 32 < cmax; cb++) {
                int jmax = cmax - cb * 32;
                if (jmax > 32) jmax = 32;
                float mv = __bfloat162float(s_m1[row * 132 + cb * 32 + lane]);
                for (int j = 0; j < jmax; j++) {
                    float m = __shfl_sync(0xffffffffu, mv, j);
                    acc += m * s_w2[(bcol + cb * 32 + j) * 32 + lane];
                }
            }
            s_m2[row * 32 + lane] = acc;
        }
        // next chunk's slab-loop __syncthreads orders m2 completion before smem reuse
    }
    __syncthreads();
    // tail: m2 relu + Wm3 + sigmoid
    for (int i2 = 0; i2 < 16; i2++) {
        int el = wid * 16 + i2;
        int e = e0 + el;
        if (e >= EE) continue;
        float m2v = fmaxf(s_m2[el * 32 + lane], 0.0f);
        float p = m2v * Wm3[lane];
#pragma unroll
        for (int o = 16; o; o >>= 1) p += __shfl_xor_sync(0xffffffffu, p, o);
        if (lane == 0) out[e] = 1.0f / (1.0f + expf(-(p + bm3[0])));
    }
}

// ------- pack Wl|Wr TRANSPOSED -> g_Wlrt[c][k], c in [0,2*dout), 32x32 smem tiles --------
__global__ void k_packWt(const float* __restrict__ Wl, const float* __restrict__ Wr,
                         int K, int dout) {
    __shared__ float tile[32][33];
    int kb = blockIdx.x * 32, cb = blockIdx.y * 32;
    int tx = threadIdx.x, ty = threadIdx.y;   // 32x8
    const float* W = (cb < dout) ? Wl : Wr;
    int csrc = (cb < dout) ? cb : cb - dout;
    for (int i = ty; i < 32; i += 8)
        tile[i][tx] = W[(size_t)(kb + i) * dout + csrc + tx];
    __syncthreads();
    for (int i = ty; i < 32; i += 8)
        g_Wlrt[(size_t)(cb + i) * K + kb + tx] = __float2bfloat16(tile[tx][i]);
}

// ---------------- fused GAT layer: alpha + online softmax + aggregation (warp/node) ------
template <int NC2>   // NC2 = dout/64
__global__ __launch_bounds__(256) void k_gat(
        const int* __restrict__ src, const float* __restrict__ ea,
        const float* __restrict__ We, const float* __restrict__ att,
        const float* __restrict__ bias, __nv_bfloat16* __restrict__ hn, int dorelu) {
    const int dout = NC2 * 64;
    __shared__ float2 sWe[ED][NC2 * 32];
    __shared__ float2 sAtt[NC2 * 32];
    __shared__ float2 sB[NC2 * 32];
    int tid = threadIdx.x;
    for (int i = tid; i < ED * dout / 2; i += 256)
        sWe[i / (dout / 2)][i % (dout / 2)] = ((const float2*)We)[i];
    for (int i = tid; i < dout / 2; i += 256) {
        sAtt[i] = ((const float2*)att)[i];
        sB[i] = ((const float2*)bias)[i];
    }
    __syncthreads();

    int lane = tid & 31, w = tid >> 5;
    int n = blockIdx.x * 8 + w;
    if (n >= NN) return;

    const __nv_bfloat16* xrp = g_xlrb + (size_t)n * 2 * dout + dout;
    float2 xrv[NC2];
#pragma unroll
    for (int q = 0; q < NC2; q++)
        xrv[q] = __bfloat1622float2(*(const __nv_bfloat162*)(xrp + q * 64 + lane * 2));

    float m = -1e30f, ssum = 0.0f;
    float2 acc[NC2];
#pragma unroll
    for (int q = 0; q < NC2; q++) acc[q] = make_float2(0.0f, 0.0f);

    int beg = g_off[n], end = g_off[n + 1];
    for (int i = beg; i < end; i++) {
        int e = g_eid[i];
        int s;
        const float* eap;
        if (e < EE) { s = src[e]; eap = ea + (size_t)e * ED; }
        else        { s = e - EE; eap = g_mean + (size_t)s * ED; }
        float eareg = (lane < ED) ? eap[lane] : 0.0f;
        const __nv_bfloat16* xlp = g_xlrb + (size_t)s * 2 * dout;
        float2 xv[NC2];
#pragma unroll
        for (int q = 0; q < NC2; q++)
            xv[q] = __bfloat1622float2(*(const __nv_bfloat162*)(xlp + q * 64 + lane * 2));
        float2 ed[NC2];
#pragma unroll
        for (int q = 0; q < NC2; q++) ed[q] = make_float2(0.0f, 0.0f);
#pragma unroll
        for (int j = 0; j < ED; j++) {
            float aj = __shfl_sync(0xffffffffu, eareg, j);
#pragma unroll
            for (int q = 0; q < NC2; q++) {
                float2 wv = sWe[j][q * 32 + lane];
                ed[q].x += aj * wv.x;
                ed[q].y += aj * wv.y;
            }
        }
        float p = 0.0f;
#pragma unroll
        for (int q = 0; q < NC2; q++) {
            float2 av = sAtt[q * 32 + lane];
            float v0 = xv[q].x + xrv[q].x + ed[q].x;
            float v1 = xv[q].y + xrv[q].y + ed[q].y;
            v0 = v0 > 0.0f ? v0 : 0.2f * v0;
            v1 = v1 > 0.0f ? v1 : 0.2f * v1;
            p += av.x * v0 + av.y * v1;
        }
#pragma unroll
        for (int o = 16; o; o >>= 1) p += __shfl_xor_sync(0xffffffffu, p, o);
        float nm = fmaxf(m, p);
        float cs = expf(m - nm);
        float ex = expf(p - nm);
        ssum = ssum * cs + ex;
#pragma unroll
        for (int q = 0; q < NC2; q++) {
            acc[q].x = acc[q].x * cs + ex * xv[q].x;
            acc[q].y = acc[q].y * cs + ex * xv[q].y;
        }
        m = nm;
    }
    float inv = 1.0f / fmaxf(ssum, 1e-16f);
    __nv_bfloat16* hp = hn + (size_t)n * dout;
#pragma unroll
    for (int q = 0; q < NC2; q++) {
        float2 bv = sB[q * 32 + lane];
        float v0 = acc[q].x * inv + bv.x;
        float v1 = acc[q].y * inv + bv.y;
        if (dorelu) { v0 = fmaxf(v0, 0.0f); v1 = fmaxf(v1, 0.0f); }
        *(uint32_t*)(hp + q * 64 + lane * 2) = bfpair(v0, v1);
    }
}

// ---- pack Wbi[k,i,j] -> TRANSPOSED g_UVt[isV*CBI + k*16 + j][i], bf16, smem transpose ----
__global__ void k_packT(const float* __restrict__ Wbi) {
    __shared__ __nv_bfloat16 sb[512 * 17];
    int k = blockIdx.x, isV = blockIdx.y, tid = threadIdx.x;
    const float* src = Wbi + ((size_t)k * 1024 + isV * 512) * 16;
#pragma unroll
    for (int q = 0; q < 8; q++) {
        int idx = tid + q * 256;
        float4 v = ((const float4*)src)[idx];
        int i = idx >> 2, j4 = (idx & 3) * 4;
        sb[i * 17 + j4 + 0] = __float2bfloat16(v.x);
        sb[i * 17 + j4 + 1] = __float2bfloat16(v.y);
        sb[i * 17 + j4 + 2] = __float2bfloat16(v.z);
        sb[i * 17 + j4 + 3] = __float2bfloat16(v.w);
    }
    __syncthreads();
#pragma unroll
    for (int q = 0; q < 16; q++) {
        int idx = tid + q * 256;
        int j = idx >> 8, ip = idx & 255, i0 = ip * 2;
        __nv_bfloat162 h2 = __halves2bfloat162(sb[i0 * 17 + j], sb[(i0 + 1) * 17 + j]);
        *(uint32_t*)(g_UVt + ((size_t)(isV * CBI + k * 16 + j)) * HMAX + i0) =
            *reinterpret_cast<uint32_t*>(&h2);
    }
}

// ---------------- pad Wm1 TRANSPOSED into [NP][KP] bf16 with bias row ----------------
__global__ void k_packM1t(const float* __restrict__ Wm1, const float* __restrict__ bm1) {
    int idx = blockIdx.x * blockDim.x + threadIdx.x;
    if (idx >= NP * KP) return;
    int o = idx / KP, r = idx % KP;
    float v = 0.0f;
    if (o < KBI) {
        if (r < KBI) v = Wm1[(size_t)r * KBI + o];
        else if (r == KBI) v = bm1[o];
    }
    g_Wm1pt[idx] = __float2bfloat16(v);
}

// ---- bilinear in CSR order (dst-sorted for L2 locality on B[dst]) ----
__global__ void k_bilin(const int* __restrict__ src, const int* __restrict__ dst,
                        const float* __restrict__ ea, const float* __restrict__ bbi) {
    int tid = threadIdx.x, w = tid >> 5, lane = tid & 31;
    int i = blockIdx.x * 8 + w;
    if (i >= EA) return;
    int e = g_eid[i];
    if (e >= EE) return;
    int s = src[e], d = dst[e];
    int j4 = lane & 3, kk = lane >> 2;
    float4 eav = *(const float4*)(ea + (size_t)e * ED + j4 * 4);
    const __nv_bfloat16* Ap = g_ABb + (size_t)s * CB2;
    const __nv_bfloat16* Bp = g_ABb + (size_t)d * CB2 + CBI;
    __nv_bfloat16* bo = g_bib + (size_t)e * KP;
#pragma unroll 4
    for (int it = 0; it < 34; it++) {
        int base = (it * 8 + kk) * 16 + j4 * 4;
        float2 a01 = __bfloat1622float2(*(const __nv_bfloat162*)(Ap + base));
        float2 a23 = __bfloat1622float2(*(const __nv_bfloat162*)(Ap + base + 2));
        float2 b01 = __bfloat1622float2(*(const __nv_bfloat162*)(Bp + base));
        float2 b23 = __bfloat1622float2(*(const __nv_bfloat162*)(Bp + base + 2));
        float v = (a01.x + b01.x) * eav.x + (a01.y + b01.y) * eav.y
                + (a23.x + b23.x) * eav.z + (a23.y + b23.y) * eav.w;
        v += __shfl_xor_sync(0xffffffffu, v, 1);
        v += __shfl_xor_sync(0xffffffffu, v, 2);
        if (j4 == 0) {
            int k = it * 8 + kk;
            bo[k] = __float2bfloat16(v + bbi[k]);
        }
    }
    if (lane < KP - KBI)
        bo[KBI + lane] = __float2bfloat16(lane == 0 ? 1.0f : 0.0f);
}

// ---------------- host ----------------
static inline dim3 gemm_grid(int M, int Nn) { return dim3(Nn / 128, (M + 127) / 128); }

extern "C" void kernel_launch(void* const* d_in, const int* in_sizes, int n_in,
                              void* d_out, int out_size) {
    const float* x         = (const float*)d_in[0];
    const float* edge_attr = (const float*)d_in[1];
    const int*   eidx      = (const int*)d_in[2];
    const int* src = eidx;
    const int* dst = eidx + EE;
    const float *Wl[4], *Wr[4], *We[4], *att[4], *bb[4];
    for (int l = 0; l < 4; l++) {
        int base = 3 + l * 5;
        Wl[l]  = (const float*)d_in[base + 0];
        Wr[l]  = (const float*)d_in[base + 1];
        We[l]  = (const float*)d_in[base + 2];
        att[l] = (const float*)d_in[base + 3];
        bb[l]  = (const float*)d_in[base + 4];
    }
    const float* Wbi = (const float*)d_in[23];
    const float* bbi = (const float*)d_in[24];
    const float* Wm1 = (const float*)d_in[25];
    const float* bm1 = (const float*)d_in[26];
    const float* Wm2 = (const float*)d_in[27];
    const float* bm2 = (const float*)d_in[28];
    const float* Wm3 = (const float*)d_in[29];
    const float* bm3 = (const float*)d_in[30];
    float* out = (float*)d_out;

    float *cnt, *msum;
    __nv_bfloat16 *xb, *h1, *h2, *xlrb, *Wlrt, *UVt, *ABb;
    int *pos;
    cudaGetSymbolAddress((void**)&xb, g_xb);
    cudaGetSymbolAddress((void**)&h1, g_h1);
    cudaGetSymbolAddress((void**)&h2, g_h2);
    cudaGetSymbolAddress((void**)&xlrb, g_xlrb);
    cudaGetSymbolAddress((void**)&Wlrt, g_Wlrt);
    cudaGetSymbolAddress((void**)&UVt, g_UVt);
    cudaGetSymbolAddress((void**)&ABb, g_ABb);
    cudaGetSymbolAddress((void**)&cnt, g_cnt);
    cudaGetSymbolAddress((void**)&msum, g_msum);
    cudaGetSymbolAddress((void**)&pos, g_pos);

    cudaFuncSetAttribute(bf16gemm<__nv_bfloat16, false>,
                         cudaFuncAttributeMaxDynamicSharedMemorySize, GSMEM);
    cudaFuncSetAttribute(k_mlp, cudaFuncAttributeMaxDynamicSharedMemorySize, ESM_TOT);

    // edge_attr mean for self loops
    cudaMemsetAsync(cnt, 0, NN * sizeof(float));
    cudaMemsetAsync(msum, 0, NN * ED * sizeof(float));
    k_count<<<(EE * ED + 255) / 256, 256>>>(dst, edge_attr);
    k_mean<<<(NN * ED + 255) / 256, 256>>>();

    // CSR build (augmented graph, keyed by dst); deg derived from cnt
    cudaMemsetAsync(pos, 0, NN * sizeof(int));
    k_scan<<<1, 1024>>>();
    k_fill<<<(EA + 255) / 256, 256>>>(dst);

    // x -> bf16
    k_cvtx<<<(NN * 32 / 2 + 255) / 256, 256>>>(x);

    const __nv_bfloat16* hcur = xb;
    int din = 32;
    __nv_bfloat16* hbufs[2] = { h1, h2 };

    for (int l = 0; l < 4; l++) {
        int dout = (l == 0) ? 256 : 512;
        k_packWt<<<dim3(din / 32, 2 * dout / 32), dim3(32, 8)>>>(Wl[l], Wr[l], din, dout);
        bf16gemm<__nv_bfloat16, false><<<gemm_grid(NN, 2 * dout), 256, GSMEM>>>(
            hcur, Wlrt, xlrb, NN, 2 * dout, din);
        __nv_bfloat16* hn = hbufs[l & 1];
        int dorelu = (l < 3) ? 1 : 0;
        if (dout == 256)
            k_gat<4><<<(NN + 7) / 8, 256>>>(src, edge_attr, We[l], att[l], bb[l], hn, dorelu);
        else
            k_gat<8><<<(NN + 7) / 8, 256>>>(src, edge_attr, We[l], att[l], bb[l], hn, dorelu);
        hcur = hn;
        din = dout;
    }

    // edge scoring
    k_packT<<<dim3(KBI, 2), 256>>>(Wbi);
    bf16gemm<__nv_bfloat16, false><<<gemm_grid(NN, CB2), 256, GSMEM>>>(
        hcur, UVt, ABb, NN, CB2, HMAX);
    k_packM1t<<<(NP * KP + 255) / 256, 256>>>(Wm1, bm1);
    k_bilin<<<(EA + 7) / 8, 256>>>(src, dst, edge_attr, bbi);
    k_mlp<<<(EE + 127) / 128, 256, ESM_TOT>>>(Wm2, bm2, Wm3, bm3, out);
}